// round 4
// baseline (speedup 1.0000x reference)
#include <cuda_runtime.h>

#define BB   64      // batch
#define TT   128     // time steps
#define INF  512     // input dim
#define XX   2048    // hidden
#define OUTF 256     // output dim
#define NBLK 128
#define NTHR 256

typedef unsigned long long ull;

// ---------------- persistent device scratch ----------------
__device__ __align__(16) float g_h0[BB * XX];
__device__ __align__(16) float g_h1[BB * XX];
__device__ __align__(16) float g_h2[BB * XX];
__device__ __align__(16) float g_h3[BB * XX];
__device__ __align__(16) float g_h4[BB * XX];
__device__ __align__(16) float g_bp[BB * XX];
__device__ __align__(16) float g_li[BB * XX];
__device__ __align__(16) float g_part[4 * BB * XX];   // 2MB: 4*64*2048 == 32*64*256
__device__ unsigned g_bar_count;
__device__ volatile unsigned g_bar_gen;

// ---------------- grid barrier (128 co-resident blocks) ----------------
__device__ __forceinline__ void grid_sync(unsigned& gen) {
    __syncthreads();
    if (threadIdx.x == 0) {
        __threadfence();                                  // release (emits CCTL.IVALL path)
        if (atomicAdd(&g_bar_count, 1u) == (unsigned)(NBLK - 1)) {
            g_bar_count = 0u;
            __threadfence();
            g_bar_gen = gen + 1u;
        } else {
            while (g_bar_gen == gen) { }
        }
        __threadfence();                                  // acquire + L1D invalidate
    }
    __syncthreads();
    ++gen;
}

// ---------------- packed fp32x2 helpers ----------------
__device__ __forceinline__ ull pack2f(float a) {
    ull r; unsigned u = __float_as_uint(a);
    asm("mov.b64 %0, {%1, %1};" : "=l"(r) : "r"(u));
    return r;
}
__device__ __forceinline__ void ffma2(ull& d, ull a, ull b) {
    asm("fma.rn.f32x2 %0, %1, %2, %0;" : "+l"(d) : "l"(a), "l"(b));
}

// ---------------- activations (match JAX) ----------------
__device__ __forceinline__ float act_fn(float h, int id) {
    switch (id) {
        case 0: return fmaxf(h, 0.0f);                         // relu
        case 1: return 1.0f / (1.0f + expf(-h));               // sigmoid
        case 2: return tanhf(h);                               // tanh
        case 3: return (h >= 0.0f) ? h : 0.1f * h;             // leaky 0.1
        default: {                                             // selu
            const float sc = 1.0507009873554804934193349852946f;
            const float al = 1.6732632423543772848170429916717f;
            return (h > 0.0f) ? sc * h : sc * al * expm1f(h);
        }
    }
}

// ---------------- GEMM stage ----------------
// out_partial[ks][b][n] = sum_{k in slice ks} A[b][k] * W[n][k]
// A is logically concat(A1, A2) along k at `asplit` (slices never straddle it).
// 128 blocks = (N/64 column tiles) x kslices.  Tile: all 64 b-rows x 64 n-cols.
__device__ __forceinline__ void gemm_stage(
    const float* __restrict__ A1, const float* __restrict__ A2,
    int lda1, int lda2, int asplit,
    const float* __restrict__ W, int ldw, int Ktot,
    int N, int kslices,
    float (*As)[16][68], float (*Ws)[16][68])
{
    const int ntile  = blockIdx.x / kslices;
    const int ks     = blockIdx.x % kslices;
    const int Kslice = Ktot / kslices;
    const int kbeg   = ks * Kslice;
    const int n0     = ntile * 64;

    const float* A; int lda;
    if (kbeg < asplit) { A = A1 + kbeg;             lda = lda1; }
    else               { A = A2 + (kbeg - asplit);  lda = lda2; }

    const int tid  = threadIdx.x;
    const int tx   = tid & 15;          // n quad
    const int ty   = tid >> 4;          // b quad
    const int lrow = tid >> 2;          // 0..63 (load row)
    const int lk4  = (tid & 3) << 2;    // 0,4,8,12 (load k quad)

    const float* Ag = A + (size_t)lrow * lda + lk4;
    const float* Wg = W + (size_t)(n0 + lrow) * ldw + kbeg + lk4;

    ull acc[4][2];
#pragma unroll
    for (int i = 0; i < 4; ++i) { acc[i][0] = 0ull; acc[i][1] = 0ull; }

    const int nchunks = Kslice >> 4;

    // preload chunk 0
    {
        float4 av = __ldcg((const float4*)Ag);
        float4 wv = __ldcg((const float4*)Wg);
        As[0][lk4 + 0][lrow] = av.x; As[0][lk4 + 1][lrow] = av.y;
        As[0][lk4 + 2][lrow] = av.z; As[0][lk4 + 3][lrow] = av.w;
        Ws[0][lk4 + 0][lrow] = wv.x; Ws[0][lk4 + 1][lrow] = wv.y;
        Ws[0][lk4 + 2][lrow] = wv.z; Ws[0][lk4 + 3][lrow] = wv.w;
    }
    __syncthreads();

    for (int c = 0; c < nchunks; ++c) {
        float4 av2, wv2;
        const bool more = (c + 1 < nchunks);
        if (more) {
            av2 = __ldcg((const float4*)(Ag + (c + 1) * 16));
            wv2 = __ldcg((const float4*)(Wg + (c + 1) * 16));
        }
        const int buf = c & 1;
#pragma unroll
        for (int k = 0; k < 16; ++k) {
            float4     a = *(const float4*)&As[buf][k][ty << 2];
            ulonglong2 w = *(const ulonglong2*)&Ws[buf][k][tx << 2];
            ull a0 = pack2f(a.x), a1 = pack2f(a.y), a2 = pack2f(a.z), a3 = pack2f(a.w);
            ffma2(acc[0][0], a0, w.x); ffma2(acc[0][1], a0, w.y);
            ffma2(acc[1][0], a1, w.x); ffma2(acc[1][1], a1, w.y);
            ffma2(acc[2][0], a2, w.x); ffma2(acc[2][1], a2, w.y);
            ffma2(acc[3][0], a3, w.x); ffma2(acc[3][1], a3, w.y);
        }
        __syncthreads();
        if (more) {
            const int nb = (c + 1) & 1;
            As[nb][lk4 + 0][lrow] = av2.x; As[nb][lk4 + 1][lrow] = av2.y;
            As[nb][lk4 + 2][lrow] = av2.z; As[nb][lk4 + 3][lrow] = av2.w;
            Ws[nb][lk4 + 0][lrow] = wv2.x; Ws[nb][lk4 + 1][lrow] = wv2.y;
            Ws[nb][lk4 + 2][lrow] = wv2.z; Ws[nb][lk4 + 3][lrow] = wv2.w;
            __syncthreads();
        }
    }

    // epilogue: write partials
    float* dst = g_part + (size_t)ks * (BB * N) + (size_t)(ty << 2) * N + n0 + (tx << 2);
#pragma unroll
    for (int i = 0; i < 4; ++i) {
        float4 o;
        o.x = __uint_as_float((unsigned)(acc[i][0]));
        o.y = __uint_as_float((unsigned)(acc[i][0] >> 32));
        o.z = __uint_as_float((unsigned)(acc[i][1]));
        o.w = __uint_as_float((unsigned)(acc[i][1] >> 32));
        *(float4*)(dst + (size_t)i * N) = o;
    }
}

// ---------------- reduce + bias + activation ----------------
__device__ __forceinline__ void reduce_stage(
    int slices, int N,
    const float* __restrict__ bias, const int* __restrict__ ids,
    float* __restrict__ dst, int dstride)
{
    const int total = BB * N;
    for (int idx = blockIdx.x * NTHR + threadIdx.x; idx < total; idx += NBLK * NTHR) {
        const int b = idx / N;
        const int n = idx - b * N;
        float s = 0.0f;
        for (int si = 0; si < slices; ++si)
            s += __ldcg(g_part + (size_t)si * total + idx);
        s += bias[n];
        dst[(size_t)b * dstride + n] = act_fn(s, ids[n]);
    }
}

// ---------------- per-row L2 normalize (block = one batch row) ----------------
__device__ __forceinline__ void row_norm(const float* __restrict__ src,
                                         float* __restrict__ dst, float* sred)
{
    const int b = blockIdx.x;                 // caller guarantees b < BB
    const float* r = src + (size_t)b * XX;
    float s = 0.0f;
    for (int j = threadIdx.x; j < XX; j += NTHR) {
        float v = __ldcg(r + j);
        s = fmaf(v, v, s);
    }
#pragma unroll
    for (int o = 16; o > 0; o >>= 1) s += __shfl_xor_sync(0xffffffffu, s, o);
    if ((threadIdx.x & 31) == 0) sred[threadIdx.x >> 5] = s;
    __syncthreads();
    if (threadIdx.x == 0) {
        float tot = 0.0f;
#pragma unroll
        for (int w = 0; w < NTHR / 32; ++w) tot += sred[w];
        sred[8] = 1.0f / fmaxf(sqrtf(tot), 1e-12f);
    }
    __syncthreads();
    const float sc = sred[8];
    for (int j = threadIdx.x; j < XX; j += NTHR)
        dst[(size_t)b * XX + j] = __ldcg(r + j) * sc;
}

// ---------------- persistent mega-kernel ----------------
__global__ void __launch_bounds__(NTHR, 1)
bnn_kernel(const float* __restrict__ x,     const float* __restrict__ Win,
           const float* __restrict__ bin,   const float* __restrict__ Wh,
           const float* __restrict__ bh,    const float* __restrict__ Wout,
           const float* __restrict__ bout,  const int* __restrict__ act_ids,
           const int* __restrict__ out_ids, float* __restrict__ out)
{
    __shared__ __align__(16) float As[2][16][68];
    __shared__ __align__(16) float Ws[2][16][68];
    __shared__ float sred[9];

    unsigned gen = g_bar_gen;   // settled value from previous launch (0 at first)

    // zero recurrent state (fresh every launch)
    for (int i = blockIdx.x * NTHR + threadIdx.x; i < BB * XX; i += NBLK * NTHR) {
        g_bp[i] = 0.0f;
        g_li[i] = 0.0f;
    }
    grid_sync(gen);

    for (int t = 0; t < TT; ++t) {
        // h0 = act(x_t @ Win^T + bin)
        gemm_stage(x + (size_t)t * INF, (const float*)0, TT * INF, 0, INF,
                   Win, INF, INF, XX, 4, As, Ws);
        grid_sync(gen);
        reduce_stage(4, XX, bin, act_ids, g_h0, XX);
        grid_sync(gen);

        // h1 = act([h0 | bp] @ Wh0^T + bh0)
        gemm_stage(g_h0, g_bp, XX, XX, XX, Wh, 2 * XX, 2 * XX, XX, 4, As, Ws);
        grid_sync(gen);
        reduce_stage(4, XX, bh, act_ids + XX, g_h1, XX);
        grid_sync(gen);

        // h2 = act([h1 | li] @ Wh1^T + bh1)
        gemm_stage(g_h1, g_li, XX, XX, XX, Wh + (size_t)1 * XX * 2 * XX,
                   2 * XX, 2 * XX, XX, 4, As, Ws);
        grid_sync(gen);
        reduce_stage(4, XX, bh + XX, act_ids + 2 * XX, g_h2, XX);
        grid_sync(gen);

        // h3 = act([h2 | h1] @ Wh2^T + bh2)
        gemm_stage(g_h2, g_h1, XX, XX, XX, Wh + (size_t)2 * XX * 2 * XX,
                   2 * XX, 2 * XX, XX, 4, As, Ws);
        grid_sync(gen);
        reduce_stage(4, XX, bh + 2 * XX, act_ids + 3 * XX, g_h3, XX);
        if (blockIdx.x < BB) row_norm(g_h2, g_li, sred);   // li = l2norm(h2)
        grid_sync(gen);

        // h4 = act([h3 | h2] @ Wh3^T + bh3)
        gemm_stage(g_h3, g_h2, XX, XX, XX, Wh + (size_t)3 * XX * 2 * XX,
                   2 * XX, 2 * XX, XX, 4, As, Ws);
        grid_sync(gen);
        reduce_stage(4, XX, bh + 3 * XX, act_ids + 4 * XX, g_h4, XX);
        grid_sync(gen);

        // y_t = act(h4 @ Wout^T + bout)
        gemm_stage(g_h4, (const float*)0, XX, 0, XX, Wout, XX, XX, OUTF, 32, As, Ws);
        grid_sync(gen);
        reduce_stage(32, OUTF, bout, out_ids, out + (size_t)t * OUTF, TT * OUTF);
        if (blockIdx.x < BB) row_norm(g_h4, g_bp, sred);   // bp = l2norm(h4)
        grid_sync(gen);
    }
}

extern "C" void kernel_launch(void* const* d_in, const int* in_sizes, int n_in,
                              void* d_out, int out_size)
{
    (void)in_sizes; (void)n_in; (void)out_size;
    const float* x        = (const float*)d_in[0];
    const float* W_in     = (const float*)d_in[1];
    const float* b_in     = (const float*)d_in[2];
    const float* W_h      = (const float*)d_in[3];
    const float* b_h      = (const float*)d_in[4];
    const float* W_out    = (const float*)d_in[5];
    const float* b_out    = (const float*)d_in[6];
    const int*   act_ids  = (const int*)d_in[7];
    const int*   out_ids  = (const int*)d_in[8];
    float*       out      = (float*)d_out;

    bnn_kernel<<<NBLK, NTHR>>>(x, W_in, b_in, W_h, b_h, W_out, b_out,
                               act_ids, out_ids, out);
}

// round 5
// speedup vs baseline: 1.2953x; 1.2953x over previous
#include <cuda_runtime.h>

#define BB   64      // batch
#define TT   128     // time steps
#define INF  512     // input dim
#define XX   2048    // hidden
#define OUTF 256     // output dim
#define NBLK 128
#define NTHR 256
#define KC   16      // k-chunk

typedef unsigned long long ull;

// ---------------- persistent device scratch ----------------
__device__ __align__(16) float g_h1[BB * XX];
__device__ __align__(16) float g_h2[BB * XX];
__device__ __align__(16) float g_h3[BB * XX];
__device__ __align__(16) float g_bp[BB * XX];
__device__ __align__(16) float g_li[BB * XX];
__device__ __align__(16) float g_part[8 * BB * XX];      // 4 MB split-K partials
__device__ __align__(16) float g_h0all[TT * BB * XX];    // 64 MB: all h0(t)
__device__ __align__(16) float g_h4all[TT * BB * XX];    // 64 MB: all h4(t)
__device__ unsigned g_bar_count;
__device__ volatile unsigned g_bar_gen;

// ---------------- grid barrier (128 co-resident blocks) ----------------
__device__ __forceinline__ void grid_sync(unsigned& gen) {
    __syncthreads();
    if (threadIdx.x == 0) {
        __threadfence();                                  // release
        if (atomicAdd(&g_bar_count, 1u) == (unsigned)(NBLK - 1)) {
            g_bar_count = 0u;
            __threadfence();
            g_bar_gen = gen + 1u;
        } else {
            while (g_bar_gen == gen) { }
        }
        __threadfence();                                  // acquire (CCTL.IVALL)
    }
    __syncthreads();
    ++gen;
}

// ---------------- packed fp32x2 helpers ----------------
__device__ __forceinline__ void ffma2(ull& d, ull a, ull b) {
    asm("fma.rn.f32x2 %0, %1, %2, %0;" : "+l"(d) : "l"(a), "l"(b));
}
__device__ __forceinline__ float4 unpack4(ull p, ull q) {
    float4 o;
    o.x = __uint_as_float((unsigned)p);
    o.y = __uint_as_float((unsigned)(p >> 32));
    o.z = __uint_as_float((unsigned)q);
    o.w = __uint_as_float((unsigned)(q >> 32));
    return o;
}

// ---------------- activations (match JAX) ----------------
__device__ __forceinline__ float act_fn(float h, int id) {
    switch (id) {
        case 0: return fmaxf(h, 0.0f);                         // relu
        case 1: return 1.0f / (1.0f + expf(-h));               // sigmoid
        case 2: return tanhf(h);                               // tanh
        case 3: return (h >= 0.0f) ? h : 0.1f * h;             // leaky 0.1
        default: {                                             // selu
            const float sc = 1.0507009873554804934193349852946f;
            const float al = 1.6732632423543772848170429916717f;
            return (h > 0.0f) ? sc * h : sc * al * expm1f(h);
        }
    }
}

// ---------------- GEMM core: 64b x 128n tile, K = nchunks*16 ----------------
// Thread tile: 4 b-rows x 8 n-cols (as 4 f32x2 pairs). A pre-duplicated in smem
// as float2{v,v} so LDS.64 yields the packed multiplier directly (no MOVs).
// Per k: 4 LDS.64 + 2 LDS.128 + 16 FFMA2.
// As2 stride 66 float2, Ws stride 132 floats (16B-aligned, <=2-way conflicts).
// nchunks must be EVEN (buffer parity makes the inter-call smem reuse safe).
__device__ __forceinline__ void gemm_core(
    const float* __restrict__ A, int lda,
    const float* __restrict__ W, int ldw,     // W pre-offset to (n0, kbeg)
    int nchunks,
    float2* __restrict__ As2, float* __restrict__ Wss,
    ull acc[4][4])
{
    const int tid  = threadIdx.x;
    const int tx   = tid & 15;
    const int ty   = tid >> 4;
    const int lrow = tid >> 2;           // 0..63
    const int lk   = (tid & 3) << 2;     // 0,4,8,12

    const float* Ag  = A + (size_t)lrow * lda + lk;
    const float* Wg0 = W + (size_t)lrow * ldw + lk;
    const float* Wg1 = W + (size_t)(lrow + 64) * ldw + lk;

#pragma unroll
    for (int i = 0; i < 4; ++i)
#pragma unroll
        for (int j = 0; j < 4; ++j) acc[i][j] = 0ull;

    // stage chunk 0
    {
        float4 av = __ldcg((const float4*)Ag);
        float4 w0 = __ldcg((const float4*)Wg0);
        float4 w1 = __ldcg((const float4*)Wg1);
        As2[(lk + 0) * 66 + lrow] = make_float2(av.x, av.x);
        As2[(lk + 1) * 66 + lrow] = make_float2(av.y, av.y);
        As2[(lk + 2) * 66 + lrow] = make_float2(av.z, av.z);
        As2[(lk + 3) * 66 + lrow] = make_float2(av.w, av.w);
        Wss[(lk + 0) * 132 + lrow] = w0.x; Wss[(lk + 1) * 132 + lrow] = w0.y;
        Wss[(lk + 2) * 132 + lrow] = w0.z; Wss[(lk + 3) * 132 + lrow] = w0.w;
        Wss[(lk + 0) * 132 + 64 + lrow] = w1.x; Wss[(lk + 1) * 132 + 64 + lrow] = w1.y;
        Wss[(lk + 2) * 132 + 64 + lrow] = w1.z; Wss[(lk + 3) * 132 + 64 + lrow] = w1.w;
    }
    __syncthreads();

    for (int c = 0; c < nchunks; ++c) {
        float4 av, w0v, w1v;
        const bool more = (c + 1 < nchunks);
        if (more) {
            av  = __ldcg((const float4*)(Ag  + (c + 1) * KC));
            w0v = __ldcg((const float4*)(Wg0 + (c + 1) * KC));
            w1v = __ldcg((const float4*)(Wg1 + (c + 1) * KC));
        }
        const float2* Ab = As2 + (c & 1) * (16 * 66);
        const float*  Wb = Wss + (c & 1) * (16 * 132);
#pragma unroll
        for (int k = 0; k < KC; ++k) {
            ull a0 = *(const ull*)(Ab + k * 66 + (ty << 2) + 0);
            ull a1 = *(const ull*)(Ab + k * 66 + (ty << 2) + 1);
            ull a2 = *(const ull*)(Ab + k * 66 + (ty << 2) + 2);
            ull a3 = *(const ull*)(Ab + k * 66 + (ty << 2) + 3);
            ulonglong2 w0 = *(const ulonglong2*)(Wb + k * 132 + (tx << 2));
            ulonglong2 w1 = *(const ulonglong2*)(Wb + k * 132 + 64 + (tx << 2));
            ffma2(acc[0][0], a0, w0.x); ffma2(acc[0][1], a0, w0.y);
            ffma2(acc[0][2], a0, w1.x); ffma2(acc[0][3], a0, w1.y);
            ffma2(acc[1][0], a1, w0.x); ffma2(acc[1][1], a1, w0.y);
            ffma2(acc[1][2], a1, w1.x); ffma2(acc[1][3], a1, w1.y);
            ffma2(acc[2][0], a2, w0.x); ffma2(acc[2][1], a2, w0.y);
            ffma2(acc[2][2], a2, w1.x); ffma2(acc[2][3], a2, w1.y);
            ffma2(acc[3][0], a3, w0.x); ffma2(acc[3][1], a3, w0.y);
            ffma2(acc[3][2], a3, w1.x); ffma2(acc[3][3], a3, w1.y);
        }
        if (more) {
            float2* Abn = As2 + ((c + 1) & 1) * (16 * 66);
            float*  Wbn = Wss + ((c + 1) & 1) * (16 * 132);
            Abn[(lk + 0) * 66 + lrow] = make_float2(av.x, av.x);
            Abn[(lk + 1) * 66 + lrow] = make_float2(av.y, av.y);
            Abn[(lk + 2) * 66 + lrow] = make_float2(av.z, av.z);
            Abn[(lk + 3) * 66 + lrow] = make_float2(av.w, av.w);
            Wbn[(lk + 0) * 132 + lrow] = w0v.x; Wbn[(lk + 1) * 132 + lrow] = w0v.y;
            Wbn[(lk + 2) * 132 + lrow] = w0v.z; Wbn[(lk + 3) * 132 + lrow] = w0v.w;
            Wbn[(lk + 0) * 132 + 64 + lrow] = w1v.x; Wbn[(lk + 1) * 132 + 64 + lrow] = w1v.y;
            Wbn[(lk + 2) * 132 + 64 + lrow] = w1v.z; Wbn[(lk + 3) * 132 + 64 + lrow] = w1v.w;
            __syncthreads();
        }
    }
}

// ---------------- hidden-layer GEMM: split-K 8, writes partials ----------------
__device__ __forceinline__ void gemm_hidden(
    const float* __restrict__ A1, const float* __restrict__ A2,
    const float* __restrict__ W, float2* As2, float* Wss)
{
    const int ntile = blockIdx.x >> 3;      // 0..15  (128 n each)
    const int ks    = blockIdx.x & 7;       // 0..7   (512 k each)
    const int kbeg  = ks << 9;
    const float* A  = (ks < 4) ? (A1 + kbeg) : (A2 + (kbeg - XX));
    const int n0    = ntile << 7;

    ull acc[4][4];
    gemm_core(A, XX, W + (size_t)n0 * (2 * XX) + kbeg, 2 * XX, 32, As2, Wss, acc);

    const int tx = threadIdx.x & 15, ty = threadIdx.x >> 4;
    float* dst = g_part + (size_t)ks * (BB * XX)
               + (size_t)(ty << 2) * XX + n0 + (tx << 2);
#pragma unroll
    for (int i = 0; i < 4; ++i) {
        *(float4*)(dst)      = unpack4(acc[i][0], acc[i][1]);
        *(float4*)(dst + 64) = unpack4(acc[i][2], acc[i][3]);
        dst += XX;
    }
}

// ---------------- reduce 8 slices + bias + act ----------------
__device__ __forceinline__ void reduce8(const float* __restrict__ bias,
                                        const int* __restrict__ ids,
                                        float* __restrict__ dst)
{
    for (int idx = blockIdx.x * NTHR + threadIdx.x; idx < BB * XX; idx += NBLK * NTHR) {
        const int n = idx & (XX - 1);
        float s = bias[n];
#pragma unroll
        for (int si = 0; si < 8; ++si)
            s += __ldcg(g_part + (size_t)si * (BB * XX) + idx);
        dst[idx] = act_fn(s, ids[n]);
    }
}

// ---------------- per-row L2 normalize ----------------
__device__ __forceinline__ void row_norm(const float* __restrict__ src,
                                         float* __restrict__ dst,
                                         float* sred, int b)
{
    const float* r = src + (size_t)b * XX;
    float s = 0.0f;
    for (int j = threadIdx.x; j < XX; j += NTHR) {
        float v = __ldcg(r + j);
        s = fmaf(v, v, s);
    }
#pragma unroll
    for (int o = 16; o > 0; o >>= 1) s += __shfl_xor_sync(0xffffffffu, s, o);
    if ((threadIdx.x & 31) == 0) sred[threadIdx.x >> 5] = s;
    __syncthreads();
    if (threadIdx.x == 0) {
        float tot = 0.0f;
#pragma unroll
        for (int w = 0; w < NTHR / 32; ++w) tot += sred[w];
        sred[8] = 1.0f / fmaxf(sqrtf(tot), 1e-12f);
    }
    __syncthreads();
    const float sc = sred[8];
    for (int j = threadIdx.x; j < XX; j += NTHR)
        dst[(size_t)b * XX + j] = __ldcg(r + j) * sc;
}

// ---------------- pre-pass: h0(t) for all t (no recurrence) ----------------
__device__ __forceinline__ void prepass(const float* __restrict__ x,
                                        const float* __restrict__ Win,
                                        const float* __restrict__ bin,
                                        const int* __restrict__ ids0,
                                        float2* As2, float* Wss)
{
    for (int tile = blockIdx.x; tile < TT * 16; tile += NBLK) {
        const int t = tile >> 4;
        const int n0 = (tile & 15) << 7;
        ull acc[4][4];
        gemm_core(x + (size_t)t * INF, TT * INF,
                  Win + (size_t)n0 * INF, INF, INF / KC, As2, Wss, acc);
        const int tx = threadIdx.x & 15, ty = threadIdx.x >> 4;
        const int nb = n0 + (tx << 2);
        float* dst = g_h0all + (size_t)t * (BB * XX)
                   + (size_t)(ty << 2) * XX + nb;
#pragma unroll
        for (int i = 0; i < 4; ++i) {
            float4 v0 = unpack4(acc[i][0], acc[i][1]);
            float4 v1 = unpack4(acc[i][2], acc[i][3]);
            v0.x = act_fn(v0.x + bin[nb + 0], ids0[nb + 0]);
            v0.y = act_fn(v0.y + bin[nb + 1], ids0[nb + 1]);
            v0.z = act_fn(v0.z + bin[nb + 2], ids0[nb + 2]);
            v0.w = act_fn(v0.w + bin[nb + 3], ids0[nb + 3]);
            v1.x = act_fn(v1.x + bin[nb + 64], ids0[nb + 64]);
            v1.y = act_fn(v1.y + bin[nb + 65], ids0[nb + 65]);
            v1.z = act_fn(v1.z + bin[nb + 66], ids0[nb + 66]);
            v1.w = act_fn(v1.w + bin[nb + 67], ids0[nb + 67]);
            *(float4*)dst = v0;
            *(float4*)(dst + 64) = v1;
            dst += XX;
        }
    }
}

// ---------------- post-pass: y(t) for all t from stored h4 ----------------
__device__ __forceinline__ void postpass(const float* __restrict__ Wout,
                                         const float* __restrict__ bout,
                                         const int* __restrict__ oids,
                                         float* __restrict__ out,
                                         float2* As2, float* Wss)
{
    for (int tile = blockIdx.x; tile < TT * 2; tile += NBLK) {
        const int t = tile >> 1;
        const int n0 = (tile & 1) << 7;
        ull acc[4][4];
        gemm_core(g_h4all + (size_t)t * (BB * XX), XX,
                  Wout + (size_t)n0 * XX, XX, XX / KC, As2, Wss, acc);
        const int tx = threadIdx.x & 15, ty = threadIdx.x >> 4;
        const int nb = n0 + (tx << 2);
#pragma unroll
        for (int i = 0; i < 4; ++i) {
            const int b = (ty << 2) + i;
            float* dst = out + (size_t)b * (TT * OUTF) + (size_t)t * OUTF + nb;
            float4 v0 = unpack4(acc[i][0], acc[i][1]);
            float4 v1 = unpack4(acc[i][2], acc[i][3]);
            v0.x = act_fn(v0.x + bout[nb + 0], oids[nb + 0]);
            v0.y = act_fn(v0.y + bout[nb + 1], oids[nb + 1]);
            v0.z = act_fn(v0.z + bout[nb + 2], oids[nb + 2]);
            v0.w = act_fn(v0.w + bout[nb + 3], oids[nb + 3]);
            v1.x = act_fn(v1.x + bout[nb + 64], oids[nb + 64]);
            v1.y = act_fn(v1.y + bout[nb + 65], oids[nb + 65]);
            v1.z = act_fn(v1.z + bout[nb + 66], oids[nb + 66]);
            v1.w = act_fn(v1.w + bout[nb + 67], oids[nb + 67]);
            *(float4*)dst = v0;
            *(float4*)(dst + 64) = v1;
        }
    }
}

// ---------------- persistent mega-kernel ----------------
__global__ void __launch_bounds__(NTHR, 1)
bnn_kernel(const float* __restrict__ x,     const float* __restrict__ Win,
           const float* __restrict__ bin,   const float* __restrict__ Wh,
           const float* __restrict__ bh,    const float* __restrict__ Wout,
           const float* __restrict__ bout,  const int* __restrict__ act_ids,
           const int* __restrict__ out_ids, float* __restrict__ out)
{
    __shared__ __align__(16) float2 As2[2 * 16 * 66];
    __shared__ __align__(16) float  Wss[2 * 16 * 132];
    __shared__ float sred[9];

    unsigned gen = g_bar_gen;   // settled value from previous launch

    // fresh recurrent state every launch
    for (int i = blockIdx.x * NTHR + threadIdx.x; i < BB * XX; i += NBLK * NTHR) {
        g_bp[i] = 0.0f;
        g_li[i] = 0.0f;
    }
    // batched input layer for all t
    prepass(x, Win, bin, act_ids, As2, Wss);
    grid_sync(gen);

    const size_t WH = (size_t)XX * 2 * XX;
    for (int t = 0; t < TT; ++t) {
        const float* h0t = g_h0all + (size_t)t * (BB * XX);
        float* h4t = g_h4all + (size_t)t * (BB * XX);

        gemm_hidden(h0t, g_bp, Wh, As2, Wss);                    // h1
        grid_sync(gen);
        reduce8(bh, act_ids + XX, g_h1);
        grid_sync(gen);

        gemm_hidden(g_h1, g_li, Wh + WH, As2, Wss);              // h2
        grid_sync(gen);
        reduce8(bh + XX, act_ids + 2 * XX, g_h2);
        grid_sync(gen);

        gemm_hidden(g_h2, g_h1, Wh + 2 * WH, As2, Wss);          // h3
        grid_sync(gen);
        reduce8(bh + 2 * XX, act_ids + 3 * XX, g_h3);
        grid_sync(gen);

        gemm_hidden(g_h3, g_h2, Wh + 3 * WH, As2, Wss);          // h4
        grid_sync(gen);
        reduce8(bh + 3 * XX, act_ids + 4 * XX, h4t);
        grid_sync(gen);

        if (blockIdx.x < BB)           row_norm(h4t,  g_bp, sred, blockIdx.x);
        else if (blockIdx.x < 2 * BB)  row_norm(g_h2, g_li, sred, blockIdx.x - BB);
        grid_sync(gen);
    }

    // batched output layer for all t
    postpass(Wout, bout, out_ids, out, As2, Wss);
}

extern "C" void kernel_launch(void* const* d_in, const int* in_sizes, int n_in,
                              void* d_out, int out_size)
{
    (void)in_sizes; (void)n_in; (void)out_size;
    const float* x        = (const float*)d_in[0];
    const float* W_in     = (const float*)d_in[1];
    const float* b_in     = (const float*)d_in[2];
    const float* W_h      = (const float*)d_in[3];
    const float* b_h      = (const float*)d_in[4];
    const float* W_out    = (const float*)d_in[5];
    const float* b_out    = (const float*)d_in[6];
    const int*   act_ids  = (const int*)d_in[7];
    const int*   out_ids  = (const int*)d_in[8];
    float*       out      = (float*)d_out;

    bnn_kernel<<<NBLK, NTHR>>>(x, W_in, b_in, W_h, b_h, W_out, b_out,
                               act_ids, out_ids, out);
}

// round 6
// speedup vs baseline: 1.5650x; 1.2083x over previous
#include <cuda_runtime.h>

#define BB   64      // batch
#define TT   128     // time steps
#define INF  512     // input dim
#define XX   2048    // hidden
#define OUTF 256     // output dim
#define NBLK 128
#define NTHR 256
#define KC   16      // k-chunk
#define KSL  16      // k slices (hidden layers)
#define NT   8       // n tiles (hidden layers, 256 wide)

typedef unsigned long long ull;

// ---------------- persistent device scratch ----------------
__device__ __align__(16) float g_h1[BB * XX];
__device__ __align__(16) float g_h2[2][BB * XX];
__device__ __align__(16) float g_h3[BB * XX];
__device__ __align__(16) float g_part[KSL * BB * XX];    // 8 MB split-K partials
__device__ __align__(16) float g_h0all[TT * BB * XX];    // all h0(t)
__device__ __align__(16) float g_h4all[TT * BB * XX];    // all h4(t)
__device__ float g_liss[2][BB];                          // sum-of-squares, parity buffered
__device__ float g_bpss[2][BB];
__device__ unsigned g_bar_count;
__device__ volatile unsigned g_bar_gen;

// smem layout (dynamic): As2 2*16*66 float2 | Wss 2*16*260 float | sred
#define AS2_BYTES (2 * 16 * 66 * 8)
#define WSS_BYTES (2 * 16 * 260 * 4)
#define SMEM_BYTES (AS2_BYTES + WSS_BYTES + 64)

// ---------------- grid barrier (128 co-resident blocks) ----------------
__device__ __forceinline__ void grid_sync(unsigned& gen) {
    __syncthreads();
    if (threadIdx.x == 0) {
        __threadfence();                                  // release
        if (atomicAdd(&g_bar_count, 1u) == (unsigned)(NBLK - 1)) {
            g_bar_count = 0u;
            __threadfence();
            g_bar_gen = gen + 1u;
        } else {
            while (g_bar_gen == gen) { }
        }
        __threadfence();                                  // acquire
    }
    __syncthreads();
    ++gen;
}

// ---------------- packed fp32x2 helpers ----------------
__device__ __forceinline__ void ffma2(ull& d, ull a, ull b) {
    asm("fma.rn.f32x2 %0, %1, %2, %0;" : "+l"(d) : "l"(a), "l"(b));
}
__device__ __forceinline__ float4 unpack4(ull p, ull q) {
    float4 o;
    o.x = __uint_as_float((unsigned)p);
    o.y = __uint_as_float((unsigned)(p >> 32));
    o.z = __uint_as_float((unsigned)q);
    o.w = __uint_as_float((unsigned)(q >> 32));
    return o;
}

// ---------------- activations (match JAX) ----------------
__device__ __forceinline__ float act_fn(float h, int id) {
    switch (id) {
        case 0: return fmaxf(h, 0.0f);
        case 1: return 1.0f / (1.0f + expf(-h));
        case 2: return tanhf(h);
        case 3: return (h >= 0.0f) ? h : 0.1f * h;
        default: {
            const float sc = 1.0507009873554804934193349852946f;
            const float al = 1.6732632423543772848170429916717f;
            return (h > 0.0f) ? sc * h : sc * al * expm1f(h);
        }
    }
}

// ---------------- GEMM core: 64b x 256n tile, thread tile 8b x 8n ----------------
// A pre-duplicated in smem as float2{v,v}: LDS.64/128 yields packed f32x2 directly.
// Per k: 4 LDS.128 (A, broadcast) + 2 LDS.128 (W) + 32 FFMA2.
// nchunks must be EVEN. A rows scaled by sc at staging (per-loader-row).
__device__ __forceinline__ void gemm_core(
    const float* __restrict__ A, int lda, float sc,
    const float* __restrict__ W, int ldw,      // W pre-offset to (n0, kbeg)
    int nchunks,
    float2* __restrict__ As2, float* __restrict__ Wss,
    ull acc[8][4])
{
    const int tid  = threadIdx.x;
    const int tx   = tid & 31;           // n  (8 cols: tx*4 and 128+tx*4)
    const int ty   = tid >> 5;           // b group of 8 rows
    const int lrow = tid >> 2;           // loader row 0..63
    const int lk   = (tid & 3) << 2;     // loader k 0,4,8,12

    const float* Ag  = A + (size_t)lrow * lda + lk;
    const float* Wg0 = W + (size_t)lrow * ldw + lk;
    const float* Wg1 = Wg0 + (size_t)64  * ldw;
    const float* Wg2 = Wg0 + (size_t)128 * ldw;
    const float* Wg3 = Wg0 + (size_t)192 * ldw;

#pragma unroll
    for (int i = 0; i < 8; ++i)
#pragma unroll
        for (int j = 0; j < 4; ++j) acc[i][j] = 0ull;

    // stage chunk 0
    {
        float4 av = __ldcg((const float4*)Ag);
        float4 w0 = __ldcg((const float4*)Wg0);
        float4 w1 = __ldcg((const float4*)Wg1);
        float4 w2 = __ldcg((const float4*)Wg2);
        float4 w3 = __ldcg((const float4*)Wg3);
        av.x *= sc; av.y *= sc; av.z *= sc; av.w *= sc;
        As2[(lk + 0) * 66 + lrow] = make_float2(av.x, av.x);
        As2[(lk + 1) * 66 + lrow] = make_float2(av.y, av.y);
        As2[(lk + 2) * 66 + lrow] = make_float2(av.z, av.z);
        As2[(lk + 3) * 66 + lrow] = make_float2(av.w, av.w);
        Wss[(lk + 0) * 260 + lrow      ] = w0.x; Wss[(lk + 1) * 260 + lrow      ] = w0.y;
        Wss[(lk + 2) * 260 + lrow      ] = w0.z; Wss[(lk + 3) * 260 + lrow      ] = w0.w;
        Wss[(lk + 0) * 260 + lrow +  64] = w1.x; Wss[(lk + 1) * 260 + lrow +  64] = w1.y;
        Wss[(lk + 2) * 260 + lrow +  64] = w1.z; Wss[(lk + 3) * 260 + lrow +  64] = w1.w;
        Wss[(lk + 0) * 260 + lrow + 128] = w2.x; Wss[(lk + 1) * 260 + lrow + 128] = w2.y;
        Wss[(lk + 2) * 260 + lrow + 128] = w2.z; Wss[(lk + 3) * 260 + lrow + 128] = w2.w;
        Wss[(lk + 0) * 260 + lrow + 192] = w3.x; Wss[(lk + 1) * 260 + lrow + 192] = w3.y;
        Wss[(lk + 2) * 260 + lrow + 192] = w3.z; Wss[(lk + 3) * 260 + lrow + 192] = w3.w;
    }
    __syncthreads();

    for (int c = 0; c < nchunks; ++c) {
        float4 av, w0v, w1v, w2v, w3v;
        const bool more = (c + 1 < nchunks);
        if (more) {
            av  = __ldcg((const float4*)(Ag  + (c + 1) * KC));
            w0v = __ldcg((const float4*)(Wg0 + (c + 1) * KC));
            w1v = __ldcg((const float4*)(Wg1 + (c + 1) * KC));
            w2v = __ldcg((const float4*)(Wg2 + (c + 1) * KC));
            w3v = __ldcg((const float4*)(Wg3 + (c + 1) * KC));
        }
        const float2* Ab = As2 + (c & 1) * (16 * 66);
        const float*  Wb = Wss + (c & 1) * (16 * 260);
#pragma unroll
        for (int k = 0; k < KC; ++k) {
            const float2* Ak = Ab + k * 66 + (ty << 3);
            ulonglong2 a01 = *(const ulonglong2*)(Ak);
            ulonglong2 a23 = *(const ulonglong2*)(Ak + 2);
            ulonglong2 a45 = *(const ulonglong2*)(Ak + 4);
            ulonglong2 a67 = *(const ulonglong2*)(Ak + 6);
            const float* Wk = Wb + k * 260 + (tx << 2);
            ulonglong2 w0 = *(const ulonglong2*)(Wk);
            ulonglong2 w1 = *(const ulonglong2*)(Wk + 128);
            ffma2(acc[0][0], a01.x, w0.x); ffma2(acc[0][1], a01.x, w0.y);
            ffma2(acc[0][2], a01.x, w1.x); ffma2(acc[0][3], a01.x, w1.y);
            ffma2(acc[1][0], a01.y, w0.x); ffma2(acc[1][1], a01.y, w0.y);
            ffma2(acc[1][2], a01.y, w1.x); ffma2(acc[1][3], a01.y, w1.y);
            ffma2(acc[2][0], a23.x, w0.x); ffma2(acc[2][1], a23.x, w0.y);
            ffma2(acc[2][2], a23.x, w1.x); ffma2(acc[2][3], a23.x, w1.y);
            ffma2(acc[3][0], a23.y, w0.x); ffma2(acc[3][1], a23.y, w0.y);
            ffma2(acc[3][2], a23.y, w1.x); ffma2(acc[3][3], a23.y, w1.y);
            ffma2(acc[4][0], a45.x, w0.x); ffma2(acc[4][1], a45.x, w0.y);
            ffma2(acc[4][2], a45.x, w1.x); ffma2(acc[4][3], a45.x, w1.y);
            ffma2(acc[5][0], a45.y, w0.x); ffma2(acc[5][1], a45.y, w0.y);
            ffma2(acc[5][2], a45.y, w1.x); ffma2(acc[5][3], a45.y, w1.y);
            ffma2(acc[6][0], a67.x, w0.x); ffma2(acc[6][1], a67.x, w0.y);
            ffma2(acc[6][2], a67.x, w1.x); ffma2(acc[6][3], a67.x, w1.y);
            ffma2(acc[7][0], a67.y, w0.x); ffma2(acc[7][1], a67.y, w0.y);
            ffma2(acc[7][2], a67.y, w1.x); ffma2(acc[7][3], a67.y, w1.y);
        }
        if (more) {
            float2* Abn = As2 + ((c + 1) & 1) * (16 * 66);
            float*  Wbn = Wss + ((c + 1) & 1) * (16 * 260);
            av.x *= sc; av.y *= sc; av.z *= sc; av.w *= sc;
            Abn[(lk + 0) * 66 + lrow] = make_float2(av.x, av.x);
            Abn[(lk + 1) * 66 + lrow] = make_float2(av.y, av.y);
            Abn[(lk + 2) * 66 + lrow] = make_float2(av.z, av.z);
            Abn[(lk + 3) * 66 + lrow] = make_float2(av.w, av.w);
            Wbn[(lk + 0) * 260 + lrow      ] = w0v.x; Wbn[(lk + 1) * 260 + lrow      ] = w0v.y;
            Wbn[(lk + 2) * 260 + lrow      ] = w0v.z; Wbn[(lk + 3) * 260 + lrow      ] = w0v.w;
            Wbn[(lk + 0) * 260 + lrow +  64] = w1v.x; Wbn[(lk + 1) * 260 + lrow +  64] = w1v.y;
            Wbn[(lk + 2) * 260 + lrow +  64] = w1v.z; Wbn[(lk + 3) * 260 + lrow +  64] = w1v.w;
            Wbn[(lk + 0) * 260 + lrow + 128] = w2v.x; Wbn[(lk + 1) * 260 + lrow + 128] = w2v.y;
            Wbn[(lk + 2) * 260 + lrow + 128] = w2v.z; Wbn[(lk + 3) * 260 + lrow + 128] = w2v.w;
            Wbn[(lk + 0) * 260 + lrow + 192] = w3v.x; Wbn[(lk + 1) * 260 + lrow + 192] = w3v.y;
            Wbn[(lk + 2) * 260 + lrow + 192] = w3v.z; Wbn[(lk + 3) * 260 + lrow + 192] = w3v.w;
            __syncthreads();
        }
    }
}

// ---------------- hidden-layer GEMM: 8 ntiles x 16 kslices, writes partials ----
// smode: 0 = no scale, 1 = scale A2 rows by 1/max(sqrt(ss[b]),1e-12), 2 = zero A2
__device__ __forceinline__ void gemm_hidden(
    const float* __restrict__ A1, const float* __restrict__ A2,
    const float* __restrict__ ss, int smode,
    const float* __restrict__ W,
    float2* As2, float* Wss)
{
    const int ntile = blockIdx.x >> 4;      // 0..7
    const int ks    = blockIdx.x & 15;      // 0..15
    const int kbeg  = ks << 8;              // *256
    const int n0    = ntile << 8;

    const float* A; float sc = 1.0f;
    if (ks < 8) {
        A = A1 + kbeg;
    } else {
        A = A2 + (kbeg - XX);
        if (smode == 2) sc = 0.0f;
        else if (smode == 1) {
            float v = __ldcg(ss + (threadIdx.x >> 2));
            sc = 1.0f / fmaxf(sqrtf(v), 1e-12f);
        }
    }

    ull acc[8][4];
    gemm_core(A, XX, sc, W + (size_t)n0 * (2 * XX) + kbeg, 2 * XX, 16, As2, Wss, acc);

    const int tx = threadIdx.x & 31, ty = threadIdx.x >> 5;
    float* dst = g_part + (size_t)ks * (BB * XX)
               + (size_t)(ty << 3) * XX + n0 + (tx << 2);
#pragma unroll
    for (int r = 0; r < 8; ++r) {
        *(float4*)(dst)       = unpack4(acc[r][0], acc[r][1]);
        *(float4*)(dst + 128) = unpack4(acc[r][2], acc[r][3]);
        dst += XX;
    }
}

// ---------------- reduce 16 slices + bias + act (+ optional row sumsq) --------
// Exactly 1 float4 per thread (128*256 threads == BB*XX/4).
__device__ __forceinline__ void reduce16(
    const float* __restrict__ bias, const int* __restrict__ ids,
    float* __restrict__ dst, float* ss_out, float* ss_zero, float* sred)
{
    const int gid = blockIdx.x * NTHR + threadIdx.x;
    if (ss_zero != nullptr && gid < BB) ss_zero[gid] = 0.0f;
    const int n = (gid & (XX / 4 - 1)) << 2;
    float4 s = *(const float4*)(bias + n);
    const float* p = g_part + ((size_t)gid << 2);
#pragma unroll
    for (int si = 0; si < KSL; ++si) {
        float4 v = __ldcg((const float4*)(p + (size_t)si * (BB * XX)));
        s.x += v.x; s.y += v.y; s.z += v.z; s.w += v.w;
    }
    const int4 id4 = *(const int4*)(ids + n);
    float4 o;
    o.x = act_fn(s.x, id4.x); o.y = act_fn(s.y, id4.y);
    o.z = act_fn(s.z, id4.z); o.w = act_fn(s.w, id4.w);
    *(float4*)(dst + ((size_t)gid << 2)) = o;

    if (ss_out != nullptr) {   // block covers half a row -> 2 commutative atomics/row
        float q = o.x * o.x + o.y * o.y + o.z * o.z + o.w * o.w;
#pragma unroll
        for (int d = 16; d > 0; d >>= 1) q += __shfl_xor_sync(0xffffffffu, q, d);
        if ((threadIdx.x & 31) == 0) sred[threadIdx.x >> 5] = q;
        __syncthreads();
        if (threadIdx.x == 0) {
            float tot = 0.0f;
#pragma unroll
            for (int w = 0; w < NTHR / 32; ++w) tot += sred[w];
            atomicAdd(ss_out + (blockIdx.x >> 1), tot);
        }
    }
}

// ---------------- pre-pass: h0(t) for all t (no recurrence) ----------------
__device__ __forceinline__ void prepass(const float* __restrict__ x,
                                        const float* __restrict__ Win,
                                        const float* __restrict__ bin,
                                        const int* __restrict__ ids0,
                                        float2* As2, float* Wss)
{
    for (int tile = blockIdx.x; tile < TT * NT; tile += NBLK) {
        const int t  = tile >> 3;
        const int n0 = (tile & 7) << 8;
        ull acc[8][4];
        gemm_core(x + (size_t)t * INF, TT * INF, 1.0f,
                  Win + (size_t)n0 * INF, INF, INF / KC, As2, Wss, acc);
        const int tx = threadIdx.x & 31, ty = threadIdx.x >> 5;
        const int c0 = n0 + (tx << 2);
        float4 b0 = *(const float4*)(bin + c0);
        float4 b1 = *(const float4*)(bin + c0 + 128);
        int4 i0 = *(const int4*)(ids0 + c0);
        int4 i1 = *(const int4*)(ids0 + c0 + 128);
        float* dst = g_h0all + (size_t)t * (BB * XX) + (size_t)(ty << 3) * XX + c0;
#pragma unroll
        for (int r = 0; r < 8; ++r) {
            float4 v0 = unpack4(acc[r][0], acc[r][1]);
            float4 v1 = unpack4(acc[r][2], acc[r][3]);
            v0.x = act_fn(v0.x + b0.x, i0.x); v0.y = act_fn(v0.y + b0.y, i0.y);
            v0.z = act_fn(v0.z + b0.z, i0.z); v0.w = act_fn(v0.w + b0.w, i0.w);
            v1.x = act_fn(v1.x + b1.x, i1.x); v1.y = act_fn(v1.y + b1.y, i1.y);
            v1.z = act_fn(v1.z + b1.z, i1.z); v1.w = act_fn(v1.w + b1.w, i1.w);
            *(float4*)dst = v0;
            *(float4*)(dst + 128) = v1;
            dst += XX;
        }
    }
}

// ---------------- post-pass: y(t) for all t from stored h4 ----------------
__device__ __forceinline__ void postpass(const float* __restrict__ Wout,
                                         const float* __restrict__ bout,
                                         const int* __restrict__ oids,
                                         float* __restrict__ out,
                                         float2* As2, float* Wss)
{
    for (int t = blockIdx.x; t < TT; t += NBLK) {
        ull acc[8][4];
        gemm_core(g_h4all + (size_t)t * (BB * XX), XX, 1.0f,
                  Wout, XX, XX / KC, As2, Wss, acc);
        const int tx = threadIdx.x & 31, ty = threadIdx.x >> 5;
        const int c0 = tx << 2;
        float4 b0 = *(const float4*)(bout + c0);
        float4 b1 = *(const float4*)(bout + c0 + 128);
        int4 i0 = *(const int4*)(oids + c0);
        int4 i1 = *(const int4*)(oids + c0 + 128);
#pragma unroll
        for (int r = 0; r < 8; ++r) {
            const int b = (ty << 3) + r;
            float* dst = out + (size_t)b * (TT * OUTF) + (size_t)t * OUTF + c0;
            float4 v0 = unpack4(acc[r][0], acc[r][1]);
            float4 v1 = unpack4(acc[r][2], acc[r][3]);
            v0.x = act_fn(v0.x + b0.x, i0.x); v0.y = act_fn(v0.y + b0.y, i0.y);
            v0.z = act_fn(v0.z + b0.z, i0.z); v0.w = act_fn(v0.w + b0.w, i0.w);
            v1.x = act_fn(v1.x + b1.x, i1.x); v1.y = act_fn(v1.y + b1.y, i1.y);
            v1.z = act_fn(v1.z + b1.z, i1.z); v1.w = act_fn(v1.w + b1.w, i1.w);
            *(float4*)dst = v0;
            *(float4*)(dst + 128) = v1;
        }
    }
}

// ---------------- persistent mega-kernel ----------------
__global__ void __launch_bounds__(NTHR, 1)
bnn_kernel(const float* __restrict__ x,     const float* __restrict__ Win,
           const float* __restrict__ bin,   const float* __restrict__ Wh,
           const float* __restrict__ bh,    const float* __restrict__ Wout,
           const float* __restrict__ bout,  const int* __restrict__ act_ids,
           const int* __restrict__ out_ids, float* __restrict__ out)
{
    extern __shared__ char smraw[];
    float2* As2  = (float2*)smraw;
    float*  Wss  = (float*)(smraw + AS2_BYTES);
    float*  sred = (float*)(smraw + AS2_BYTES + WSS_BYTES);

    unsigned gen = g_bar_gen;   // settled value from previous launch

    // zero sumsq accumulators (fresh every launch)
    if (blockIdx.x == 0 && threadIdx.x < 2 * BB) {
        ((float*)g_liss)[threadIdx.x] = 0.0f;
        ((float*)g_bpss)[threadIdx.x] = 0.0f;
    }
    prepass(x, Win, bin, act_ids, As2, Wss);
    grid_sync(gen);

    const size_t WH = (size_t)XX * 2 * XX;
    for (int t = 0; t < TT; ++t) {
        const int p = t & 1, q = p ^ 1;
        const float* h0t    = g_h0all + (size_t)t * (BB * XX);
        float*       h4t    = g_h4all + (size_t)t * (BB * XX);
        const float* h4prev = (t > 0) ? (h4t - BB * XX) : g_h4all;
        const int sm = (t > 0) ? 1 : 2;

        // h1 = act([h0 | l2norm(h4(t-1))] @ Wh0^T + bh0)
        gemm_hidden(h0t, h4prev, (const float*)g_bpss[q], sm, Wh, As2, Wss);
        grid_sync(gen);
        reduce16(bh, act_ids + XX, g_h1, nullptr, nullptr, sred);
        grid_sync(gen);

        // h2 = act([h1 | l2norm(h2(t-1))] @ Wh1^T + bh1)
        gemm_hidden(g_h1, g_h2[q], (const float*)g_liss[q], sm, Wh + WH, As2, Wss);
        grid_sync(gen);
        reduce16(bh + XX, act_ids + 2 * XX, g_h2[p],
                 (float*)g_liss[p], (float*)g_liss[q], sred);
        grid_sync(gen);

        // h3 = act([h2 | h1] @ Wh2^T + bh2)
        gemm_hidden(g_h2[p], g_h1, nullptr, 0, Wh + 2 * WH, As2, Wss);
        grid_sync(gen);
        reduce16(bh + 2 * XX, act_ids + 3 * XX, g_h3, nullptr, nullptr, sred);
        grid_sync(gen);

        // h4 = act([h3 | h2] @ Wh3^T + bh3)
        gemm_hidden(g_h3, g_h2[p], nullptr, 0, Wh + 3 * WH, As2, Wss);
        grid_sync(gen);
        reduce16(bh + 3 * XX, act_ids + 4 * XX, h4t,
                 (float*)g_bpss[p], (float*)g_bpss[q], sred);
        grid_sync(gen);
    }

    postpass(Wout, bout, out_ids, out, As2, Wss);
}

extern "C" void kernel_launch(void* const* d_in, const int* in_sizes, int n_in,
                              void* d_out, int out_size)
{
    (void)in_sizes; (void)n_in; (void)out_size;
    const float* x        = (const float*)d_in[0];
    const float* W_in     = (const float*)d_in[1];
    const float* b_in     = (const float*)d_in[2];
    const float* W_h      = (const float*)d_in[3];
    const float* b_h      = (const float*)d_in[4];
    const float* W_out    = (const float*)d_in[5];
    const float* b_out    = (const float*)d_in[6];
    const int*   act_ids  = (const int*)d_in[7];
    const int*   out_ids  = (const int*)d_in[8];
    float*       out      = (float*)d_out;

    cudaFuncSetAttribute(bnn_kernel, cudaFuncAttributeMaxDynamicSharedMemorySize,
                         SMEM_BYTES);
    bnn_kernel<<<NBLK, NTHR, SMEM_BYTES>>>(x, W_in, b_in, W_h, b_h, W_out, b_out,
                                           act_ids, out_ids, out);
}

// round 7
// speedup vs baseline: 1.5675x; 1.0016x over previous
#include <cuda_runtime.h>

#define BB   64      // batch
#define TT   128     // time steps
#define INF  512     // input dim
#define XX   2048    // hidden
#define OUTF 256     // output dim
#define NBLK 128
#define NTHR 256
#define KC   16      // k-chunk
#define KSL  16      // k slices (hidden layers)
#define NT   8       // n tiles (hidden layers, 256 wide)

typedef unsigned long long ull;

// ---------------- persistent device scratch ----------------
__device__ __align__(16) float g_h1[BB * XX];
__device__ __align__(16) float g_h2[2][BB * XX];
__device__ __align__(16) float g_h3[BB * XX];
__device__ __align__(16) float g_part[KSL * BB * XX];    // 8 MB split-K partials
__device__ __align__(16) float g_h0all[TT * BB * XX];    // all h0(t)
__device__ __align__(16) float g_h4all[TT * BB * XX];    // all h4(t)
__device__ float g_liss[2][BB];                          // sum-of-squares, parity buffered
__device__ float g_bpss[2][BB];
__device__ unsigned g_bar_count;
__device__ volatile unsigned g_bar_gen;

// smem layout (dynamic): As2 2*16*66 float2 | Wss 2*16*260 float | sred
#define AS2_BYTES (2 * 16 * 66 * 8)
#define WSS_BYTES (2 * 16 * 260 * 4)
#define SMEM_BYTES (AS2_BYTES + WSS_BYTES + 64)

// ---------------- grid barrier (128 co-resident blocks) ----------------
__device__ __forceinline__ void grid_sync(unsigned& gen) {
    __syncthreads();
    if (threadIdx.x == 0) {
        __threadfence();                                  // release
        if (atomicAdd(&g_bar_count, 1u) == (unsigned)(NBLK - 1)) {
            g_bar_count = 0u;
            __threadfence();
            g_bar_gen = gen + 1u;
        } else {
            while (g_bar_gen == gen) { }
        }
        __threadfence();                                  // acquire
    }
    __syncthreads();
    ++gen;
}

// ---------------- packed fp32x2 helpers ----------------
__device__ __forceinline__ void ffma2(ull& d, ull a, ull b) {
    asm("fma.rn.f32x2 %0, %1, %2, %0;" : "+l"(d) : "l"(a), "l"(b));
}
__device__ __forceinline__ float4 unpack4(ull p, ull q) {
    float4 o;
    o.x = __uint_as_float((unsigned)p);
    o.y = __uint_as_float((unsigned)(p >> 32));
    o.z = __uint_as_float((unsigned)q);
    o.w = __uint_as_float((unsigned)(q >> 32));
    return o;
}

// ---------------- activations (match JAX) ----------------
__device__ __forceinline__ float act_fn(float h, int id) {
    switch (id) {
        case 0: return fmaxf(h, 0.0f);
        case 1: return 1.0f / (1.0f + expf(-h));
        case 2: return tanhf(h);
        case 3: return (h >= 0.0f) ? h : 0.1f * h;
        default: {
            const float sc = 1.0507009873554804934193349852946f;
            const float al = 1.6732632423543772848170429916717f;
            return (h > 0.0f) ? sc * h : sc * al * expm1f(h);
        }
    }
}

// ---------------- GEMM core: 64b x 256n tile, thread tile 8b x 8n ----------------
// A pre-duplicated in smem as float2{v,v}: LDS.64/128 yields packed f32x2 directly.
// Per k: 4 LDS.128 (A, broadcast) + 2 LDS.128 (W) + 32 FFMA2.
// nchunks must be EVEN. A rows scaled by sc at staging (per-loader-row).
__device__ __forceinline__ void gemm_core(
    const float* __restrict__ A, int lda, float sc,
    const float* __restrict__ W, int ldw,      // W pre-offset to (n0, kbeg)
    int nchunks,
    float2* __restrict__ As2, float* __restrict__ Wss,
    ull acc[8][4])
{
    const int tid  = threadIdx.x;
    const int tx   = tid & 31;           // n  (8 cols: tx*4 and 128+tx*4)
    const int ty   = tid >> 5;           // b group of 8 rows
    const int lrow = tid >> 2;           // loader row 0..63
    const int lk   = (tid & 3) << 2;     // loader k 0,4,8,12

    const float* Ag  = A + (size_t)lrow * lda + lk;
    const float* Wg0 = W + (size_t)lrow * ldw + lk;
    const float* Wg1 = Wg0 + (size_t)64  * ldw;
    const float* Wg2 = Wg0 + (size_t)128 * ldw;
    const float* Wg3 = Wg0 + (size_t)192 * ldw;

#pragma unroll
    for (int i = 0; i < 8; ++i)
#pragma unroll
        for (int j = 0; j < 4; ++j) acc[i][j] = 0ull;

    // stage chunk 0
    {
        float4 av = __ldcg((const float4*)Ag);
        float4 w0 = __ldcg((const float4*)Wg0);
        float4 w1 = __ldcg((const float4*)Wg1);
        float4 w2 = __ldcg((const float4*)Wg2);
        float4 w3 = __ldcg((const float4*)Wg3);
        av.x *= sc; av.y *= sc; av.z *= sc; av.w *= sc;
        As2[(lk + 0) * 66 + lrow] = make_float2(av.x, av.x);
        As2[(lk + 1) * 66 + lrow] = make_float2(av.y, av.y);
        As2[(lk + 2) * 66 + lrow] = make_float2(av.z, av.z);
        As2[(lk + 3) * 66 + lrow] = make_float2(av.w, av.w);
        Wss[(lk + 0) * 260 + lrow      ] = w0.x; Wss[(lk + 1) * 260 + lrow      ] = w0.y;
        Wss[(lk + 2) * 260 + lrow      ] = w0.z; Wss[(lk + 3) * 260 + lrow      ] = w0.w;
        Wss[(lk + 0) * 260 + lrow +  64] = w1.x; Wss[(lk + 1) * 260 + lrow +  64] = w1.y;
        Wss[(lk + 2) * 260 + lrow +  64] = w1.z; Wss[(lk + 3) * 260 + lrow +  64] = w1.w;
        Wss[(lk + 0) * 260 + lrow + 128] = w2.x; Wss[(lk + 1) * 260 + lrow + 128] = w2.y;
        Wss[(lk + 2) * 260 + lrow + 128] = w2.z; Wss[(lk + 3) * 260 + lrow + 128] = w2.w;
        Wss[(lk + 0) * 260 + lrow + 192] = w3.x; Wss[(lk + 1) * 260 + lrow + 192] = w3.y;
        Wss[(lk + 2) * 260 + lrow + 192] = w3.z; Wss[(lk + 3) * 260 + lrow + 192] = w3.w;
    }
    __syncthreads();

    for (int c = 0; c < nchunks; ++c) {
        float4 av, w0v, w1v, w2v, w3v;
        const bool more = (c + 1 < nchunks);
        if (more) {
            av  = __ldcg((const float4*)(Ag  + (c + 1) * KC));
            w0v = __ldcg((const float4*)(Wg0 + (c + 1) * KC));
            w1v = __ldcg((const float4*)(Wg1 + (c + 1) * KC));
            w2v = __ldcg((const float4*)(Wg2 + (c + 1) * KC));
            w3v = __ldcg((const float4*)(Wg3 + (c + 1) * KC));
        }
        const float2* Ab = As2 + (c & 1) * (16 * 66);
        const float*  Wb = Wss + (c & 1) * (16 * 260);
#pragma unroll
        for (int k = 0; k < KC; ++k) {
            const float2* Ak = Ab + k * 66 + (ty << 3);
            ulonglong2 a01 = *(const ulonglong2*)(Ak);
            ulonglong2 a23 = *(const ulonglong2*)(Ak + 2);
            ulonglong2 a45 = *(const ulonglong2*)(Ak + 4);
            ulonglong2 a67 = *(const ulonglong2*)(Ak + 6);
            const float* Wk = Wb + k * 260 + (tx << 2);
            ulonglong2 w0 = *(const ulonglong2*)(Wk);
            ulonglong2 w1 = *(const ulonglong2*)(Wk + 128);
            ffma2(acc[0][0], a01.x, w0.x); ffma2(acc[0][1], a01.x, w0.y);
            ffma2(acc[0][2], a01.x, w1.x); ffma2(acc[0][3], a01.x, w1.y);
            ffma2(acc[1][0], a01.y, w0.x); ffma2(acc[1][1], a01.y, w0.y);
            ffma2(acc[1][2], a01.y, w1.x); ffma2(acc[1][3], a01.y, w1.y);
            ffma2(acc[2][0], a23.x, w0.x); ffma2(acc[2][1], a23.x, w0.y);
            ffma2(acc[2][2], a23.x, w1.x); ffma2(acc[2][3], a23.x, w1.y);
            ffma2(acc[3][0], a23.y, w0.x); ffma2(acc[3][1], a23.y, w0.y);
            ffma2(acc[3][2], a23.y, w1.x); ffma2(acc[3][3], a23.y, w1.y);
            ffma2(acc[4][0], a45.x, w0.x); ffma2(acc[4][1], a45.x, w0.y);
            ffma2(acc[4][2], a45.x, w1.x); ffma2(acc[4][3], a45.x, w1.y);
            ffma2(acc[5][0], a45.y, w0.x); ffma2(acc[5][1], a45.y, w0.y);
            ffma2(acc[5][2], a45.y, w1.x); ffma2(acc[5][3], a45.y, w1.y);
            ffma2(acc[6][0], a67.x, w0.x); ffma2(acc[6][1], a67.x, w0.y);
            ffma2(acc[6][2], a67.x, w1.x); ffma2(acc[6][3], a67.x, w1.y);
            ffma2(acc[7][0], a67.y, w0.x); ffma2(acc[7][1], a67.y, w0.y);
            ffma2(acc[7][2], a67.y, w1.x); ffma2(acc[7][3], a67.y, w1.y);
        }
        if (more) {
            float2* Abn = As2 + ((c + 1) & 1) * (16 * 66);
            float*  Wbn = Wss + ((c + 1) & 1) * (16 * 260);
            av.x *= sc; av.y *= sc; av.z *= sc; av.w *= sc;
            Abn[(lk + 0) * 66 + lrow] = make_float2(av.x, av.x);
            Abn[(lk + 1) * 66 + lrow] = make_float2(av.y, av.y);
            Abn[(lk + 2) * 66 + lrow] = make_float2(av.z, av.z);
            Abn[(lk + 3) * 66 + lrow] = make_float2(av.w, av.w);
            Wbn[(lk + 0) * 260 + lrow      ] = w0v.x; Wbn[(lk + 1) * 260 + lrow      ] = w0v.y;
            Wbn[(lk + 2) * 260 + lrow      ] = w0v.z; Wbn[(lk + 3) * 260 + lrow      ] = w0v.w;
            Wbn[(lk + 0) * 260 + lrow +  64] = w1v.x; Wbn[(lk + 1) * 260 + lrow +  64] = w1v.y;
            Wbn[(lk + 2) * 260 + lrow +  64] = w1v.z; Wbn[(lk + 3) * 260 + lrow +  64] = w1v.w;
            Wbn[(lk + 0) * 260 + lrow + 128] = w2v.x; Wbn[(lk + 1) * 260 + lrow + 128] = w2v.y;
            Wbn[(lk + 2) * 260 + lrow + 128] = w2v.z; Wbn[(lk + 3) * 260 + lrow + 128] = w2v.w;
            Wbn[(lk + 0) * 260 + lrow + 192] = w3v.x; Wbn[(lk + 1) * 260 + lrow + 192] = w3v.y;
            Wbn[(lk + 2) * 260 + lrow + 192] = w3v.z; Wbn[(lk + 3) * 260 + lrow + 192] = w3v.w;
            __syncthreads();
        }
    }
}

// ---------------- hidden-layer GEMM: 8 ntiles x 16 kslices, writes partials ----
// smode: 0 = no scale, 1 = scale A2 rows by 1/max(sqrt(ss[b]),1e-12), 2 = zero A2
__device__ __forceinline__ void gemm_hidden(
    const float* __restrict__ A1, const float* __restrict__ A2,
    const float* __restrict__ ss, int smode,
    const float* __restrict__ W,
    float2* As2, float* Wss)
{
    const int ntile = blockIdx.x >> 4;      // 0..7
    const int ks    = blockIdx.x & 15;      // 0..15
    const int kbeg  = ks << 8;              // *256
    const int n0    = ntile << 8;

    const float* A; float sc = 1.0f;
    if (ks < 8) {
        A = A1 + kbeg;
    } else {
        A = A2 + (kbeg - XX);
        if (smode == 2) sc = 0.0f;
        else if (smode == 1) {
            float v = __ldcg(ss + (threadIdx.x >> 2));
            sc = 1.0f / fmaxf(sqrtf(v), 1e-12f);
        }
    }

    ull acc[8][4];
    gemm_core(A, XX, sc, W + (size_t)n0 * (2 * XX) + kbeg, 2 * XX, 16, As2, Wss, acc);

    const int tx = threadIdx.x & 31, ty = threadIdx.x >> 5;
    float* dst = g_part + (size_t)ks * (BB * XX)
               + (size_t)(ty << 3) * XX + n0 + (tx << 2);
#pragma unroll
    for (int r = 0; r < 8; ++r) {
        *(float4*)(dst)       = unpack4(acc[r][0], acc[r][1]);
        *(float4*)(dst + 128) = unpack4(acc[r][2], acc[r][3]);
        dst += XX;
    }
}

// ---------------- reduce 16 slices + bias + act (+ optional row sumsq) --------
// Exactly 1 float4 per thread (128*256 threads == BB*XX/4).
__device__ __forceinline__ void reduce16(
    const float* __restrict__ bias, const int* __restrict__ ids,
    float* __restrict__ dst, float* ss_out, float* ss_zero, float* sred)
{
    const int gid = blockIdx.x * NTHR + threadIdx.x;
    if (ss_zero != nullptr && gid < BB) ss_zero[gid] = 0.0f;
    const int n = (gid & (XX / 4 - 1)) << 2;
    float4 s = *(const float4*)(bias + n);
    const float* p = g_part + ((size_t)gid << 2);
#pragma unroll
    for (int si = 0; si < KSL; ++si) {
        float4 v = __ldcg((const float4*)(p + (size_t)si * (BB * XX)));
        s.x += v.x; s.y += v.y; s.z += v.z; s.w += v.w;
    }
    const int4 id4 = *(const int4*)(ids + n);
    float4 o;
    o.x = act_fn(s.x, id4.x); o.y = act_fn(s.y, id4.y);
    o.z = act_fn(s.z, id4.z); o.w = act_fn(s.w, id4.w);
    *(float4*)(dst + ((size_t)gid << 2)) = o;

    if (ss_out != nullptr) {   // block covers half a row -> 2 commutative atomics/row
        float q = o.x * o.x + o.y * o.y + o.z * o.z + o.w * o.w;
#pragma unroll
        for (int d = 16; d > 0; d >>= 1) q += __shfl_xor_sync(0xffffffffu, q, d);
        if ((threadIdx.x & 31) == 0) sred[threadIdx.x >> 5] = q;
        __syncthreads();
        if (threadIdx.x == 0) {
            float tot = 0.0f;
#pragma unroll
            for (int w = 0; w < NTHR / 32; ++w) tot += sred[w];
            atomicAdd(ss_out + (blockIdx.x >> 1), tot);
        }
    }
}

// ---------------- pre-pass: h0(t) for all t (no recurrence) ----------------
__device__ __forceinline__ void prepass(const float* __restrict__ x,
                                        const float* __restrict__ Win,
                                        const float* __restrict__ bin,
                                        const int* __restrict__ ids0,
                                        float2* As2, float* Wss)
{
    for (int tile = blockIdx.x; tile < TT * NT; tile += NBLK) {
        const int t  = tile >> 3;
        const int n0 = (tile & 7) << 8;
        ull acc[8][4];
        gemm_core(x + (size_t)t * INF, TT * INF, 1.0f,
                  Win + (size_t)n0 * INF, INF, INF / KC, As2, Wss, acc);
        const int tx = threadIdx.x & 31, ty = threadIdx.x >> 5;
        const int c0 = n0 + (tx << 2);
        float4 b0 = *(const float4*)(bin + c0);
        float4 b1 = *(const float4*)(bin + c0 + 128);
        int4 i0 = *(const int4*)(ids0 + c0);
        int4 i1 = *(const int4*)(ids0 + c0 + 128);
        float* dst = g_h0all + (size_t)t * (BB * XX) + (size_t)(ty << 3) * XX + c0;
#pragma unroll
        for (int r = 0; r < 8; ++r) {
            float4 v0 = unpack4(acc[r][0], acc[r][1]);
            float4 v1 = unpack4(acc[r][2], acc[r][3]);
            v0.x = act_fn(v0.x + b0.x, i0.x); v0.y = act_fn(v0.y + b0.y, i0.y);
            v0.z = act_fn(v0.z + b0.z, i0.z); v0.w = act_fn(v0.w + b0.w, i0.w);
            v1.x = act_fn(v1.x + b1.x, i1.x); v1.y = act_fn(v1.y + b1.y, i1.y);
            v1.z = act_fn(v1.z + b1.z, i1.z); v1.w = act_fn(v1.w + b1.w, i1.w);
            *(float4*)dst = v0;
            *(float4*)(dst + 128) = v1;
            dst += XX;
        }
    }
}

// ---------------- post-pass: y(t) for all t from stored h4 ----------------
__device__ __forceinline__ void postpass(const float* __restrict__ Wout,
                                         const float* __restrict__ bout,
                                         const int* __restrict__ oids,
                                         float* __restrict__ out,
                                         float2* As2, float* Wss)
{
    for (int t = blockIdx.x; t < TT; t += NBLK) {
        ull acc[8][4];
        gemm_core(g_h4all + (size_t)t * (BB * XX), XX, 1.0f,
                  Wout, XX, XX / KC, As2, Wss, acc);
        const int tx = threadIdx.x & 31, ty = threadIdx.x >> 5;
        const int c0 = tx << 2;
        float4 b0 = *(const float4*)(bout + c0);
        float4 b1 = *(const float4*)(bout + c0 + 128);
        int4 i0 = *(const int4*)(oids + c0);
        int4 i1 = *(const int4*)(oids + c0 + 128);
#pragma unroll
        for (int r = 0; r < 8; ++r) {
            const int b = (ty << 3) + r;
            float* dst = out + (size_t)b * (TT * OUTF) + (size_t)t * OUTF + c0;
            float4 v0 = unpack4(acc[r][0], acc[r][1]);
            float4 v1 = unpack4(acc[r][2], acc[r][3]);
            v0.x = act_fn(v0.x + b0.x, i0.x); v0.y = act_fn(v0.y + b0.y, i0.y);
            v0.z = act_fn(v0.z + b0.z, i0.z); v0.w = act_fn(v0.w + b0.w, i0.w);
            v1.x = act_fn(v1.x + b1.x, i1.x); v1.y = act_fn(v1.y + b1.y, i1.y);
            v1.z = act_fn(v1.z + b1.z, i1.z); v1.w = act_fn(v1.w + b1.w, i1.w);
            *(float4*)dst = v0;
            *(float4*)(dst + 128) = v1;
        }
    }
}

// ---------------- persistent mega-kernel ----------------
__global__ void __launch_bounds__(NTHR, 1)
bnn_kernel(const float* __restrict__ x,     const float* __restrict__ Win,
           const float* __restrict__ bin,   const float* __restrict__ Wh,
           const float* __restrict__ bh,    const float* __restrict__ Wout,
           const float* __restrict__ bout,  const int* __restrict__ act_ids,
           const int* __restrict__ out_ids, float* __restrict__ out)
{
    extern __shared__ char smraw[];
    float2* As2  = (float2*)smraw;
    float*  Wss  = (float*)(smraw + AS2_BYTES);
    float*  sred = (float*)(smraw + AS2_BYTES + WSS_BYTES);

    unsigned gen = g_bar_gen;   // settled value from previous launch

    // zero sumsq accumulators (fresh every launch)
    if (blockIdx.x == 0 && threadIdx.x < 2 * BB) {
        ((float*)g_liss)[threadIdx.x] = 0.0f;
        ((float*)g_bpss)[threadIdx.x] = 0.0f;
    }
    prepass(x, Win, bin, act_ids, As2, Wss);
    grid_sync(gen);

    const size_t WH = (size_t)XX * 2 * XX;
    for (int t = 0; t < TT; ++t) {
        const int p = t & 1, q = p ^ 1;
        const float* h0t    = g_h0all + (size_t)t * (BB * XX);
        float*       h4t    = g_h4all + (size_t)t * (BB * XX);
        const float* h4prev = (t > 0) ? (h4t - BB * XX) : g_h4all;
        const int sm = (t > 0) ? 1 : 2;

        // h1 = act([h0 | l2norm(h4(t-1))] @ Wh0^T + bh0)
        gemm_hidden(h0t, h4prev, (const float*)g_bpss[q], sm, Wh, As2, Wss);
        grid_sync(gen);
        reduce16(bh, act_ids + XX, g_h1, nullptr, nullptr, sred);
        grid_sync(gen);

        // h2 = act([h1 | l2norm(h2(t-1))] @ Wh1^T + bh1)
        gemm_hidden(g_h1, g_h2[q], (const float*)g_liss[q], sm, Wh + WH, As2, Wss);
        grid_sync(gen);
        reduce16(bh + XX, act_ids + 2 * XX, g_h2[p],
                 (float*)g_liss[p], (float*)g_liss[q], sred);
        grid_sync(gen);

        // h3 = act([h2 | h1] @ Wh2^T + bh2)
        gemm_hidden(g_h2[p], g_h1, nullptr, 0, Wh + 2 * WH, As2, Wss);
        grid_sync(gen);
        reduce16(bh + 2 * XX, act_ids + 3 * XX, g_h3, nullptr, nullptr, sred);
        grid_sync(gen);

        // h4 = act([h3 | h2] @ Wh3^T + bh3)
        gemm_hidden(g_h3, g_h2[p], nullptr, 0, Wh + 3 * WH, As2, Wss);
        grid_sync(gen);
        reduce16(bh + 3 * XX, act_ids + 4 * XX, h4t,
                 (float*)g_bpss[p], (float*)g_bpss[q], sred);
        grid_sync(gen);
    }

    postpass(Wout, bout, out_ids, out, As2, Wss);
}

extern "C" void kernel_launch(void* const* d_in, const int* in_sizes, int n_in,
                              void* d_out, int out_size)
{
    (void)in_sizes; (void)n_in; (void)out_size;
    const float* x        = (const float*)d_in[0];
    const float* W_in     = (const float*)d_in[1];
    const float* b_in     = (const float*)d_in[2];
    const float* W_h      = (const float*)d_in[3];
    const float* b_h      = (const float*)d_in[4];
    const float* W_out    = (const float*)d_in[5];
    const float* b_out    = (const float*)d_in[6];
    const int*   act_ids  = (const int*)d_in[7];
    const int*   out_ids  = (const int*)d_in[8];
    float*       out      = (float*)d_out;

    cudaFuncSetAttribute(bnn_kernel, cudaFuncAttributeMaxDynamicSharedMemorySize,
                         SMEM_BYTES);
    bnn_kernel<<<NBLK, NTHR, SMEM_BYTES>>>(x, W_in, b_in, W_h, b_h, W_out, b_out,
                                           act_ids, out_ids, out);
}

// round 10
// speedup vs baseline: 2.5013x; 1.5958x over previous
#include <cuda_runtime.h>
#include <cuda_bf16.h>
#include <cstdint>

#define BB   64
#define TT   128
#define INF  512
#define XX   2048
#define OUTF 256
#define NBLK 128
#define NTHR 256
#define KC   16
#define KSL  8

typedef unsigned long long ull;

// ---------------- persistent device scratch ----------------
__device__ __align__(16) float g_h1[BB * XX];
__device__ __align__(16) float g_h2[2][BB * XX];
__device__ __align__(16) float g_h3[BB * XX];
__device__ __align__(16) float g_part[KSL * BB * XX];
__device__ __align__(16) float g_h0all[TT * BB * XX];
__device__ __align__(16) float g_h4all[TT * BB * XX];
__device__ __align__(16) __nv_bfloat16 g_Whh[4ull * XX * 2 * XX];  // 64MB hi
__device__ __align__(16) __nv_bfloat16 g_Whl[4ull * XX * 2 * XX];  // 64MB lo
__device__ float g_liss[2][BB];
__device__ float g_bpss[2][BB];
__device__ unsigned g_bar_count;
__device__ volatile unsigned g_bar_gen;

// smem (relative to 1024-aligned base):
//  [0,96K): MMA tiles, 2 bufs x 48K {Ahi 8K | Alo 8K | Bhi 16K | Blo 16K}
//           (SIMT pre/post overlays As2/Wss in its own phases)
//  98304: sred
#define TILE_BUF 49152
#define A_HI 0
#define A_LO 8192
#define B_HI 16384
#define B_LO 32768
#define OFF_SRED 98304
#define AS2_BYTES (2 * 16 * 66 * 8)
#define SMEM_BYTES (98304 + 2048)

// ---------------- grid barrier ----------------
__device__ __forceinline__ void grid_sync(unsigned& gen) {
    __syncthreads();
    if (threadIdx.x == 0) {
        __threadfence();
        if (atomicAdd(&g_bar_count, 1u) == (unsigned)(NBLK - 1)) {
            g_bar_count = 0u;
            __threadfence();
            g_bar_gen = gen + 1u;
        } else {
            while (g_bar_gen == gen) { }
        }
        __threadfence();
    }
    __syncthreads();
    ++gen;
}

// ---------------- small helpers ----------------
__device__ __forceinline__ uint32_t smem_u32(const void* p) {
    uint32_t a;
    asm("{ .reg .u64 t; cvta.to.shared.u64 t, %1; cvt.u32.u64 %0, t; }" : "=r"(a) : "l"(p));
    return a;
}
__device__ __forceinline__ void ffma2(ull& d, ull a, ull b) {
    asm("fma.rn.f32x2 %0, %1, %2, %0;" : "+l"(d) : "l"(a), "l"(b));
}
__device__ __forceinline__ float4 unpack4(ull p, ull q) {
    float4 o;
    o.x = __uint_as_float((unsigned)p);  o.y = __uint_as_float((unsigned)(p >> 32));
    o.z = __uint_as_float((unsigned)q);  o.w = __uint_as_float((unsigned)(q >> 32));
    return o;
}
__device__ __forceinline__ unsigned pkbf(float a, float b) {
    return (unsigned)__bfloat16_as_ushort(__float2bfloat16(a))
         | ((unsigned)__bfloat16_as_ushort(__float2bfloat16(b)) << 16);
}
__device__ __forceinline__ float bfof(float a) {
    return __bfloat162float(__float2bfloat16(a));
}
__device__ __forceinline__ float act_fn(float h, int id) {
    switch (id) {
        case 0: return fmaxf(h, 0.0f);
        case 1: return 1.0f / (1.0f + expf(-h));
        case 2: return tanhf(h);
        case 3: return (h >= 0.0f) ? h : 0.1f * h;
        default: {
            const float sc = 1.0507009873554804934193349852946f;
            const float al = 1.6732632423543772848170429916717f;
            return (h > 0.0f) ? sc * h : sc * al * expm1f(h);
        }
    }
}

// ---------------- tensor-core primitives (baseline PTX, sm_80+) ----------------
__device__ __forceinline__ void ldsm4(uint32_t* r, uint32_t addr) {
    asm volatile("ldmatrix.sync.aligned.m8n8.x4.shared.b16 {%0,%1,%2,%3}, [%4];"
                 : "=r"(r[0]), "=r"(r[1]), "=r"(r[2]), "=r"(r[3]) : "r"(addr));
}
__device__ __forceinline__ void mma16816(float* c, const uint32_t* a, const uint32_t* b) {
    asm volatile(
        "mma.sync.aligned.m16n8k16.row.col.f32.bf16.bf16.f32 "
        "{%0,%1,%2,%3}, {%4,%5,%6,%7}, {%8,%9}, {%0,%1,%2,%3};"
        : "+f"(c[0]), "+f"(c[1]), "+f"(c[2]), "+f"(c[3])
        : "r"(a[0]), "r"(a[1]), "r"(a[2]), "r"(a[3]), "r"(b[0]), "r"(b[1]));
}
// swizzled byte offset for rows of 128B, 16B granules: col16 ^= row&7
__device__ __forceinline__ uint32_t swz(int row, int c16) {
    return (uint32_t)(((row << 3) + (c16 ^ (row & 7))) << 4);
}

// ================= hidden-layer GEMM via mma.sync =================
// D[b=64 (M), n=128 (N)] partial over K=512 slice, K chunks of 64, dbl-buffered.
// 3-pass hi/lo split: Ahi*Bhi + Ahi*Blo + Alo*Bhi.
__device__ __forceinline__ void gemm_hidden_tc(
    const float* __restrict__ A1, const float* __restrict__ A2,
    const float* __restrict__ ss, int smode,
    const __nv_bfloat16* __restrict__ Whh_l, const __nv_bfloat16* __restrict__ Whl_l,
    char* tiles, uint32_t tu0)
{
    const int ntile = blockIdx.x >> 3;   // 0..15 (128 n each)
    const int ks    = blockIdx.x & 7;    // 0..7  (K=512 each)
    const int n0    = ntile << 7;
    const int kbeg  = ks << 9;

    const float* Asrc; int sm;
    if (kbeg < XX) { Asrc = A1 + kbeg; sm = 0; }
    else           { Asrc = A2 + (kbeg - XX); sm = smode; }
    const __nv_bfloat16* WhP = Whh_l + kbeg;
    const __nv_bfloat16* WlP = Whl_l + kbeg;

    const int tid = threadIdx.x, lane = tid & 31, warp = tid >> 5;
    const int wx = warp & 3, wy = warp >> 2;     // n-quad, m-half

    float acc[2][4][4];
#pragma unroll
    for (int i = 0; i < 2; ++i)
#pragma unroll
        for (int t = 0; t < 4; ++t)
#pragma unroll
            for (int e = 0; e < 4; ++e) acc[i][t][e] = 0.0f;

    // per-thread staging unit coords
    const int au_row0 = tid >> 3,        au_c16 = tid & 7;     // A: 2 units (row, row+32)
    const int bu_row0 = tid >> 3,        bu_c16 = tid & 7;     // B: 4 units (row + 32*r)

    float4 av[2][2]; float asc[2];
    uint4 wh[4], wl[4];

    // ---- load chunk 0 into regs ----
#pragma unroll
    for (int r = 0; r < 2; ++r) {
        const int row = au_row0 + (r << 5);
        float sc = 1.0f;
        if (sm == 2) sc = 0.0f;
        else if (sm == 1) { float v = __ldcg(ss + row); sc = 1.0f / fmaxf(sqrtf(v), 1e-12f); }
        asc[r] = sc;
        const float* s = Asrc + (size_t)row * XX + (au_c16 << 3);
        av[r][0] = __ldcg((const float4*)s);
        av[r][1] = __ldcg((const float4*)(s + 4));
    }
#pragma unroll
    for (int r = 0; r < 4; ++r) {
        const int row = bu_row0 + (r << 5);
        const size_t gp = (size_t)(n0 + row) * (2 * XX) + (bu_c16 << 3);
        wh[r] = __ldcg((const uint4*)(WhP + gp));
        wl[r] = __ldcg((const uint4*)(WlP + gp));
    }

    for (int c = 0; c < 8; ++c) {
        const int buf = c & 1;
        char* base = tiles + buf * TILE_BUF;
        // ---- store staged regs to smem buf ----
#pragma unroll
        for (int r = 0; r < 2; ++r) {
            const int row = au_row0 + (r << 5);
            float f[8] = {av[r][0].x * asc[r], av[r][0].y * asc[r], av[r][0].z * asc[r], av[r][0].w * asc[r],
                          av[r][1].x * asc[r], av[r][1].y * asc[r], av[r][1].z * asc[r], av[r][1].w * asc[r]};
            float hf[8];
#pragma unroll
            for (int i = 0; i < 8; ++i) hf[i] = bfof(f[i]);
            uint4 H = make_uint4(pkbf(f[0], f[1]), pkbf(f[2], f[3]), pkbf(f[4], f[5]), pkbf(f[6], f[7]));
            uint4 L = make_uint4(pkbf(f[0] - hf[0], f[1] - hf[1]), pkbf(f[2] - hf[2], f[3] - hf[3]),
                                 pkbf(f[4] - hf[4], f[5] - hf[5]), pkbf(f[6] - hf[6], f[7] - hf[7]));
            const uint32_t o = swz(row, au_c16);
            *(uint4*)(base + A_HI + o) = H;
            *(uint4*)(base + A_LO + o) = L;
        }
#pragma unroll
        for (int r = 0; r < 4; ++r) {
            const int row = bu_row0 + (r << 5);
            const uint32_t o = swz(row, bu_c16);
            *(uint4*)(base + B_HI + o) = wh[r];
            *(uint4*)(base + B_LO + o) = wl[r];
        }
        __syncthreads();

        // ---- prefetch next chunk into regs (overlaps with mma) ----
        if (c < 7) {
            const int cn = c + 1;
#pragma unroll
            for (int r = 0; r < 2; ++r) {
                const int row = au_row0 + (r << 5);
                const float* s = Asrc + (size_t)row * XX + (cn << 6) + (au_c16 << 3);
                av[r][0] = __ldcg((const float4*)s);
                av[r][1] = __ldcg((const float4*)(s + 4));
            }
#pragma unroll
            for (int r = 0; r < 4; ++r) {
                const int row = bu_row0 + (r << 5);
                const size_t gp = (size_t)(n0 + row) * (2 * XX) + (cn << 6) + (bu_c16 << 3);
                wh[r] = __ldcg((const uint4*)(WhP + gp));
                wl[r] = __ldcg((const uint4*)(WlP + gp));
            }
        }

        // ---- compute on buf: 4 k16 steps ----
        const uint32_t sb = tu0 + buf * TILE_BUF;
        const int arow = lane & 15, acb = lane >> 4;
        const int brow = (lane & 7) + ((lane >> 4) << 3), bcb = (lane >> 3) & 1;
#pragma unroll
        for (int kk = 0; kk < 4; ++kk) {
            uint32_t ah[2][4], al_[2][4], bh[2][4], bl_[2][4];
#pragma unroll
            for (int i = 0; i < 2; ++i) {
                const int row = wy * 32 + i * 16 + arow;
                const uint32_t o = swz(row, kk * 2 + acb);
                ldsm4(ah[i],  sb + A_HI + o);
                ldsm4(al_[i], sb + A_LO + o);
            }
#pragma unroll
            for (int j = 0; j < 2; ++j) {
                const int row = wx * 32 + j * 16 + brow;
                const uint32_t o = swz(row, kk * 2 + bcb);
                ldsm4(bh[j],  sb + B_HI + o);
                ldsm4(bl_[j], sb + B_LO + o);
            }
#pragma unroll
            for (int i = 0; i < 2; ++i)
#pragma unroll
                for (int j = 0; j < 2; ++j) {
                    mma16816(acc[i][2 * j],     ah[i],  &bh[j][0]);
                    mma16816(acc[i][2 * j + 1], ah[i],  &bh[j][2]);
                    mma16816(acc[i][2 * j],     ah[i],  &bl_[j][0]);
                    mma16816(acc[i][2 * j + 1], ah[i],  &bl_[j][2]);
                    mma16816(acc[i][2 * j],     al_[i], &bh[j][0]);
                    mma16816(acc[i][2 * j + 1], al_[i], &bh[j][2]);
                }
        }
        __syncthreads();
    }

    // ---- epilogue: write split-K partials ----
    float* dst = g_part + (size_t)ks * (BB * XX) + n0;
#pragma unroll
    for (int i = 0; i < 2; ++i) {
        const int row = wy * 32 + i * 16 + (lane >> 2);
#pragma unroll
        for (int t = 0; t < 4; ++t) {
            const int col = wx * 32 + t * 8 + (lane & 3) * 2;
            *(float2*)(dst + (size_t)row * XX + col)       = make_float2(acc[i][t][0], acc[i][t][1]);
            *(float2*)(dst + (size_t)(row + 8) * XX + col) = make_float2(acc[i][t][2], acc[i][t][3]);
        }
    }
}

// ---------------- reduce 8 slices + bias + act (+ optional row sumsq) --------
__device__ __forceinline__ void reduce8(
    const float* __restrict__ bias, const int* __restrict__ ids,
    float* __restrict__ dst, float* ss_out, float* ss_zero, float* sred)
{
    const int gid = blockIdx.x * NTHR + threadIdx.x;
    if (ss_zero != nullptr && gid < BB) ss_zero[gid] = 0.0f;
    const int n = (gid & (XX / 4 - 1)) << 2;
    float4 s = *(const float4*)(bias + n);
    const float* p = g_part + ((size_t)gid << 2);
#pragma unroll
    for (int si = 0; si < KSL; ++si) {
        float4 v = __ldcg((const float4*)(p + (size_t)si * (BB * XX)));
        s.x += v.x; s.y += v.y; s.z += v.z; s.w += v.w;
    }
    const int4 id4 = *(const int4*)(ids + n);
    float4 o;
    o.x = act_fn(s.x, id4.x); o.y = act_fn(s.y, id4.y);
    o.z = act_fn(s.z, id4.z); o.w = act_fn(s.w, id4.w);
    *(float4*)(dst + ((size_t)gid << 2)) = o;

    if (ss_out != nullptr) {
        float q = o.x * o.x + o.y * o.y + o.z * o.z + o.w * o.w;
#pragma unroll
        for (int d = 16; d > 0; d >>= 1) q += __shfl_xor_sync(0xffffffffu, q, d);
        if ((threadIdx.x & 31) == 0) sred[threadIdx.x >> 5] = q;
        __syncthreads();
        if (threadIdx.x == 0) {
            float tot = 0.0f;
#pragma unroll
            for (int w = 0; w < NTHR / 32; ++w) tot += sred[w];
            atomicAdd(ss_out + (blockIdx.x >> 1), tot);
        }
    }
}

// ---------------- weight hi/lo split (once per launch) ----------------
__device__ __forceinline__ void wconv(const float* __restrict__ W) {
    const size_t n = 4ull * XX * 2 * XX;
    for (size_t i = ((size_t)blockIdx.x * NTHR + threadIdx.x) * 4; i < n;
         i += (size_t)NBLK * NTHR * 4) {
        float4 v = __ldcg((const float4*)(W + i));
        float hx = bfof(v.x), hy = bfof(v.y), hz = bfof(v.z), hw = bfof(v.w);
        uint2 H = make_uint2(pkbf(v.x, v.y), pkbf(v.z, v.w));
        uint2 L = make_uint2(pkbf(v.x - hx, v.y - hy), pkbf(v.z - hz, v.w - hw));
        *(uint2*)((char*)g_Whh + 2 * i) = H;
        *(uint2*)((char*)g_Whl + 2 * i) = L;
    }
}

// ================= SIMT pre/post pass (proven R5 path) =================
__device__ __forceinline__ void gemm_core(
    const float* __restrict__ A, int lda, float sc,
    const float* __restrict__ W, int ldw, int nchunks,
    float2* __restrict__ As2, float* __restrict__ Wss, ull acc[8][4])
{
    const int tid = threadIdx.x;
    const int tx = tid & 31, ty = tid >> 5;
    const int lrow = tid >> 2, lk = (tid & 3) << 2;
    const float* Ag  = A + (size_t)lrow * lda + lk;
    const float* Wg0 = W + (size_t)lrow * ldw + lk;
    const float* Wg1 = Wg0 + (size_t)64  * ldw;
    const float* Wg2 = Wg0 + (size_t)128 * ldw;
    const float* Wg3 = Wg0 + (size_t)192 * ldw;
#pragma unroll
    for (int i = 0; i < 8; ++i)
#pragma unroll
        for (int j = 0; j < 4; ++j) acc[i][j] = 0ull;
    {
        float4 av = __ldcg((const float4*)Ag);
        float4 w0 = __ldcg((const float4*)Wg0), w1 = __ldcg((const float4*)Wg1);
        float4 w2 = __ldcg((const float4*)Wg2), w3 = __ldcg((const float4*)Wg3);
        av.x *= sc; av.y *= sc; av.z *= sc; av.w *= sc;
        As2[(lk+0)*66+lrow] = make_float2(av.x, av.x); As2[(lk+1)*66+lrow] = make_float2(av.y, av.y);
        As2[(lk+2)*66+lrow] = make_float2(av.z, av.z); As2[(lk+3)*66+lrow] = make_float2(av.w, av.w);
        Wss[(lk+0)*260+lrow] = w0.x; Wss[(lk+1)*260+lrow] = w0.y; Wss[(lk+2)*260+lrow] = w0.z; Wss[(lk+3)*260+lrow] = w0.w;
        Wss[(lk+0)*260+lrow+64] = w1.x; Wss[(lk+1)*260+lrow+64] = w1.y; Wss[(lk+2)*260+lrow+64] = w1.z; Wss[(lk+3)*260+lrow+64] = w1.w;
        Wss[(lk+0)*260+lrow+128] = w2.x; Wss[(lk+1)*260+lrow+128] = w2.y; Wss[(lk+2)*260+lrow+128] = w2.z; Wss[(lk+3)*260+lrow+128] = w2.w;
        Wss[(lk+0)*260+lrow+192] = w3.x; Wss[(lk+1)*260+lrow+192] = w3.y; Wss[(lk+2)*260+lrow+192] = w3.z; Wss[(lk+3)*260+lrow+192] = w3.w;
    }
    __syncthreads();
    for (int c = 0; c < nchunks; ++c) {
        float4 av, w0v, w1v, w2v, w3v;
        const bool more = (c + 1 < nchunks);
        if (more) {
            av  = __ldcg((const float4*)(Ag  + (c + 1) * KC));
            w0v = __ldcg((const float4*)(Wg0 + (c + 1) * KC));
            w1v = __ldcg((const float4*)(Wg1 + (c + 1) * KC));
            w2v = __ldcg((const float4*)(Wg2 + (c + 1) * KC));
            w3v = __ldcg((const float4*)(Wg3 + (c + 1) * KC));
        }
        const float2* Ab = As2 + (c & 1) * (16 * 66);
        const float*  Wb = Wss + (c & 1) * (16 * 260);
#pragma unroll
        for (int k = 0; k < KC; ++k) {
            const float2* Ak = Ab + k * 66 + (ty << 3);
            ulonglong2 a01 = *(const ulonglong2*)(Ak);
            ulonglong2 a23 = *(const ulonglong2*)(Ak + 2);
            ulonglong2 a45 = *(const ulonglong2*)(Ak + 4);
            ulonglong2 a67 = *(const ulonglong2*)(Ak + 6);
            const float* Wk = Wb + k * 260 + (tx << 2);
            ulonglong2 w0 = *(const ulonglong2*)(Wk);
            ulonglong2 w1 = *(const ulonglong2*)(Wk + 128);
            ffma2(acc[0][0], a01.x, w0.x); ffma2(acc[0][1], a01.x, w0.y);
            ffma2(acc[0][2], a01.x, w1.x); ffma2(acc[0][3], a01.x, w1.y);
            ffma2(acc[1][0], a01.y, w0.x); ffma2(acc[1][1], a01.y, w0.y);
            ffma2(acc[1][2], a01.y, w1.x); ffma2(acc[1][3], a01.y, w1.y);
            ffma2(acc[2][0], a23.x, w0.x); ffma2(acc[2][1], a23.x, w0.y);
            ffma2(acc[2][2], a23.x, w1.x); ffma2(acc[2][3], a23.x, w1.y);
            ffma2(acc[3][0], a23.y, w0.x); ffma2(acc[3][1], a23.y, w0.y);
            ffma2(acc[3][2], a23.y, w1.x); ffma2(acc[3][3], a23.y, w1.y);
            ffma2(acc[4][0], a45.x, w0.x); ffma2(acc[4][1], a45.x, w0.y);
            ffma2(acc[4][2], a45.x, w1.x); ffma2(acc[4][3], a45.x, w1.y);
            ffma2(acc[5][0], a45.y, w0.x); ffma2(acc[5][1], a45.y, w0.y);
            ffma2(acc[5][2], a45.y, w1.x); ffma2(acc[5][3], a45.y, w1.y);
            ffma2(acc[6][0], a67.x, w0.x); ffma2(acc[6][1], a67.x, w0.y);
            ffma2(acc[6][2], a67.x, w1.x); ffma2(acc[6][3], a67.x, w1.y);
            ffma2(acc[7][0], a67.y, w0.x); ffma2(acc[7][1], a67.y, w0.y);
            ffma2(acc[7][2], a67.y, w1.x); ffma2(acc[7][3], a67.y, w1.y);
        }
        if (more) {
            float2* Abn = As2 + ((c + 1) & 1) * (16 * 66);
            float*  Wbn = Wss + ((c + 1) & 1) * (16 * 260);
            av.x *= sc; av.y *= sc; av.z *= sc; av.w *= sc;
            Abn[(lk+0)*66+lrow] = make_float2(av.x, av.x); Abn[(lk+1)*66+lrow] = make_float2(av.y, av.y);
            Abn[(lk+2)*66+lrow] = make_float2(av.z, av.z); Abn[(lk+3)*66+lrow] = make_float2(av.w, av.w);
            Wbn[(lk+0)*260+lrow] = w0v.x; Wbn[(lk+1)*260+lrow] = w0v.y; Wbn[(lk+2)*260+lrow] = w0v.z; Wbn[(lk+3)*260+lrow] = w0v.w;
            Wbn[(lk+0)*260+lrow+64] = w1v.x; Wbn[(lk+1)*260+lrow+64] = w1v.y; Wbn[(lk+2)*260+lrow+64] = w1v.z; Wbn[(lk+3)*260+lrow+64] = w1v.w;
            Wbn[(lk+0)*260+lrow+128] = w2v.x; Wbn[(lk+1)*260+lrow+128] = w2v.y; Wbn[(lk+2)*260+lrow+128] = w2v.z; Wbn[(lk+3)*260+lrow+128] = w2v.w;
            Wbn[(lk+0)*260+lrow+192] = w3v.x; Wbn[(lk+1)*260+lrow+192] = w3v.y; Wbn[(lk+2)*260+lrow+192] = w3v.z; Wbn[(lk+3)*260+lrow+192] = w3v.w;
            __syncthreads();
        }
    }
}

__device__ __forceinline__ void prepass(const float* __restrict__ x,
                                        const float* __restrict__ Win,
                                        const float* __restrict__ bin,
                                        const int* __restrict__ ids0,
                                        float2* As2, float* Wss)
{
    for (int tile = blockIdx.x; tile < TT * 8; tile += NBLK) {
        const int t = tile >> 3, n0 = (tile & 7) << 8;
        ull acc[8][4];
        gemm_core(x + (size_t)t * INF, TT * INF, 1.0f,
                  Win + (size_t)n0 * INF, INF, INF / KC, As2, Wss, acc);
        const int tx = threadIdx.x & 31, ty = threadIdx.x >> 5;
        const int c0 = n0 + (tx << 2);
        float4 b0 = *(const float4*)(bin + c0), b1 = *(const float4*)(bin + c0 + 128);
        int4 i0 = *(const int4*)(ids0 + c0), i1 = *(const int4*)(ids0 + c0 + 128);
        float* dst = g_h0all + (size_t)t * (BB * XX) + (size_t)(ty << 3) * XX + c0;
#pragma unroll
        for (int r = 0; r < 8; ++r) {
            float4 v0 = unpack4(acc[r][0], acc[r][1]);
            float4 v1 = unpack4(acc[r][2], acc[r][3]);
            v0.x = act_fn(v0.x + b0.x, i0.x); v0.y = act_fn(v0.y + b0.y, i0.y);
            v0.z = act_fn(v0.z + b0.z, i0.z); v0.w = act_fn(v0.w + b0.w, i0.w);
            v1.x = act_fn(v1.x + b1.x, i1.x); v1.y = act_fn(v1.y + b1.y, i1.y);
            v1.z = act_fn(v1.z + b1.z, i1.z); v1.w = act_fn(v1.w + b1.w, i1.w);
            *(float4*)dst = v0; *(float4*)(dst + 128) = v1;
            dst += XX;
        }
    }
}

__device__ __forceinline__ void postpass(const float* __restrict__ Wout,
                                         const float* __restrict__ bout,
                                         const int* __restrict__ oids,
                                         float* __restrict__ out,
                                         float2* As2, float* Wss)
{
    for (int t = blockIdx.x; t < TT; t += NBLK) {
        ull acc[8][4];
        gemm_core(g_h4all + (size_t)t * (BB * XX), XX, 1.0f, Wout, XX, XX / KC, As2, Wss, acc);
        const int tx = threadIdx.x & 31, ty = threadIdx.x >> 5;
        const int c0 = tx << 2;
        float4 b0 = *(const float4*)(bout + c0), b1 = *(const float4*)(bout + c0 + 128);
        int4 i0 = *(const int4*)(oids + c0), i1 = *(const int4*)(oids + c0 + 128);
#pragma unroll
        for (int r = 0; r < 8; ++r) {
            const int b = (ty << 3) + r;
            float* dst = out + (size_t)b * (TT * OUTF) + (size_t)t * OUTF + c0;
            float4 v0 = unpack4(acc[r][0], acc[r][1]);
            float4 v1 = unpack4(acc[r][2], acc[r][3]);
            v0.x = act_fn(v0.x + b0.x, i0.x); v0.y = act_fn(v0.y + b0.y, i0.y);
            v0.z = act_fn(v0.z + b0.z, i0.z); v0.w = act_fn(v0.w + b0.w, i0.w);
            v1.x = act_fn(v1.x + b1.x, i1.x); v1.y = act_fn(v1.y + b1.y, i1.y);
            v1.z = act_fn(v1.z + b1.z, i1.z); v1.w = act_fn(v1.w + b1.w, i1.w);
            *(float4*)dst = v0; *(float4*)(dst + 128) = v1;
        }
    }
}

// ---------------- persistent mega-kernel ----------------
__global__ void __launch_bounds__(NTHR, 1)
bnn_kernel(const float* __restrict__ x,     const float* __restrict__ Win,
           const float* __restrict__ bin,   const float* __restrict__ Wh,
           const float* __restrict__ bh,    const float* __restrict__ Wout,
           const float* __restrict__ bout,  const int* __restrict__ act_ids,
           const int* __restrict__ out_ids, float* __restrict__ out)
{
    extern __shared__ char smraw[];
    const uint32_t sbase = smem_u32(smraw);
    const uint32_t tu0 = (sbase + 1023u) & ~1023u;
    char* tiles = smraw + (tu0 - sbase);
    float* sred = (float*)(tiles + OFF_SRED);
    float2* As2 = (float2*)tiles;
    float*  Wss = (float*)(tiles + AS2_BYTES);

    unsigned gen = g_bar_gen;

    if (blockIdx.x == 0 && threadIdx.x < 2 * BB) {
        ((float*)g_liss)[threadIdx.x] = 0.0f;
        ((float*)g_bpss)[threadIdx.x] = 0.0f;
    }
    wconv(Wh);
    prepass(x, Win, bin, act_ids, As2, Wss);
    grid_sync(gen);

    const size_t WH = (size_t)XX * 2 * XX;
    for (int t = 0; t < TT; ++t) {
        const int p = t & 1, q = p ^ 1;
        const float* h0t = g_h0all + (size_t)t * (BB * XX);
        float* h4t = g_h4all + (size_t)t * (BB * XX);
        const float* h4prev = (t > 0) ? (h4t - BB * XX) : g_h4all;
        const int sm = (t > 0) ? 1 : 2;

        gemm_hidden_tc(h0t, h4prev, (const float*)g_bpss[q], sm,
                       g_Whh, g_Whl, tiles, tu0);
        grid_sync(gen);
        reduce8(bh, act_ids + XX, g_h1, nullptr, nullptr, sred);
        grid_sync(gen);

        gemm_hidden_tc(g_h1, g_h2[q], (const float*)g_liss[q], sm,
                       g_Whh + WH, g_Whl + WH, tiles, tu0);
        grid_sync(gen);
        reduce8(bh + XX, act_ids + 2 * XX, g_h2[p],
                (float*)g_liss[p], (float*)g_liss[q], sred);
        grid_sync(gen);

        gemm_hidden_tc(g_h2[p], g_h1, nullptr, 0,
                       g_Whh + 2 * WH, g_Whl + 2 * WH, tiles, tu0);
        grid_sync(gen);
        reduce8(bh + 2 * XX, act_ids + 3 * XX, g_h3, nullptr, nullptr, sred);
        grid_sync(gen);

        gemm_hidden_tc(g_h3, g_h2[p], nullptr, 0,
                       g_Whh + 3 * WH, g_Whl + 3 * WH, tiles, tu0);
        grid_sync(gen);
        reduce8(bh + 3 * XX, act_ids + 4 * XX, h4t,
                (float*)g_bpss[p], (float*)g_bpss[q], sred);
        grid_sync(gen);
    }

    postpass(Wout, bout, out_ids, out, As2, Wss);
}

extern "C" void kernel_launch(void* const* d_in, const int* in_sizes, int n_in,
                              void* d_out, int out_size)
{
    (void)in_sizes; (void)n_in; (void)out_size;
    const float* x       = (const float*)d_in[0];
    const float* W_in    = (const float*)d_in[1];
    const float* b_in    = (const float*)d_in[2];
    const float* W_h     = (const float*)d_in[3];
    const float* b_h     = (const float*)d_in[4];
    const float* W_out   = (const float*)d_in[5];
    const float* b_out   = (const float*)d_in[6];
    const int*   act_ids = (const int*)d_in[7];
    const int*   out_ids = (const int*)d_in[8];
    float*       out     = (float*)d_out;

    cudaFuncSetAttribute(bnn_kernel, cudaFuncAttributeMaxDynamicSharedMemorySize,
                         SMEM_BYTES);
    bnn_kernel<<<NBLK, NTHR, SMEM_BYTES>>>(x, W_in, b_in, W_h, b_h, W_out, b_out,
                                           act_ids, out_ids, out);
}

// round 11
// speedup vs baseline: 2.9367x; 1.1741x over previous
#include <cuda_runtime.h>
#include <cuda_bf16.h>
#include <cstdint>

#define BB   64
#define TT   128
#define INF  512
#define XX   2048
#define OUTF 256
#define NBLK 128
#define NTHR 512
#define KC   16
#define KSL  8
#define BBXX (BB * XX)

typedef unsigned long long ull;
typedef __nv_bfloat16 bf16;

// ---------------- persistent device scratch ----------------
__device__ __align__(16) float g_part[KSL * BBXX];
__device__ __align__(16) float g_h4all[TT * BBXX];            // fp32 for postpass
__device__ __align__(16) bf16  g_h0H[TT * BBXX], g_h0L[TT * BBXX];
__device__ __align__(16) bf16  g_h4H[TT * BBXX], g_h4L[TT * BBXX];
__device__ __align__(16) bf16  g_h1H[BBXX], g_h1L[BBXX];
__device__ __align__(16) bf16  g_h2H[2][BBXX], g_h2L[2][BBXX];
__device__ __align__(16) bf16  g_h3H[BBXX], g_h3L[BBXX];
__device__ __align__(16) bf16  g_WhH[4ull * XX * 2 * XX];     // 64MB hi
__device__ __align__(16) bf16  g_WhL[4ull * XX * 2 * XX];     // 64MB lo
__device__ float g_liss[2][BB];
__device__ float g_bpss[2][BB];
__device__ unsigned g_bar_count;
__device__ volatile unsigned g_bar_gen;

// smem (rel. to 1024-aligned base): 2 bufs x 48K {Ahi 8K|Alo 8K|Bhi 16K|Blo 16K}
// SIMT pre/post overlays As2/Wss.  sred at 98304.
#define TILE_BUF 49152
#define A_HI 0
#define A_LO 8192
#define B_HI 16384
#define B_LO 32768
#define OFF_SRED 98304
#define AS2_BYTES (2 * 16 * 66 * 8)
#define SMEM_BYTES (98304 + 2048 + 1024)

// ---------------- grid barrier ----------------
__device__ __forceinline__ void grid_sync(unsigned& gen) {
    __syncthreads();
    if (threadIdx.x == 0) {
        __threadfence();
        if (atomicAdd(&g_bar_count, 1u) == (unsigned)(NBLK - 1)) {
            g_bar_count = 0u;
            __threadfence();
            g_bar_gen = gen + 1u;
        } else {
            while (g_bar_gen == gen) { }
        }
        __threadfence();
    }
    __syncthreads();
    ++gen;
}

// ---------------- helpers ----------------
__device__ __forceinline__ uint32_t smem_u32(const void* p) {
    uint32_t a;
    asm("{ .reg .u64 t; cvta.to.shared.u64 t, %1; cvt.u32.u64 %0, t; }" : "=r"(a) : "l"(p));
    return a;
}
__device__ __forceinline__ void ffma2(ull& d, ull a, ull b) {
    asm("fma.rn.f32x2 %0, %1, %2, %0;" : "+l"(d) : "l"(a), "l"(b));
}
__device__ __forceinline__ float4 unpack4(ull p, ull q) {
    float4 o;
    o.x = __uint_as_float((unsigned)p);  o.y = __uint_as_float((unsigned)(p >> 32));
    o.z = __uint_as_float((unsigned)q);  o.w = __uint_as_float((unsigned)(q >> 32));
    return o;
}
__device__ __forceinline__ unsigned pkbf(float a, float b) {
    return (unsigned)__bfloat16_as_ushort(__float2bfloat16(a))
         | ((unsigned)__bfloat16_as_ushort(__float2bfloat16(b)) << 16);
}
__device__ __forceinline__ float bfof(float a) {
    return __bfloat162float(__float2bfloat16(a));
}
__device__ __forceinline__ float act_fn(float h, int id) {
    switch (id) {
        case 0: return fmaxf(h, 0.0f);
        case 1: return 1.0f / (1.0f + expf(-h));
        case 2: return tanhf(h);
        case 3: return (h >= 0.0f) ? h : 0.1f * h;
        default: {
            const float sc = 1.0507009873554804934193349852946f;
            const float al = 1.6732632423543772848170429916717f;
            return (h > 0.0f) ? sc * h : sc * al * expm1f(h);
        }
    }
}

// ---------------- tensor-core / async primitives (baseline PTX) ----------------
__device__ __forceinline__ void ldsm4(uint32_t* r, uint32_t addr) {
    asm volatile("ldmatrix.sync.aligned.m8n8.x4.shared.b16 {%0,%1,%2,%3}, [%4];"
                 : "=r"(r[0]), "=r"(r[1]), "=r"(r[2]), "=r"(r[3]) : "r"(addr));
}
__device__ __forceinline__ void mma16816(float* c, const uint32_t* a, const uint32_t* b) {
    asm volatile(
        "mma.sync.aligned.m16n8k16.row.col.f32.bf16.bf16.f32 "
        "{%0,%1,%2,%3}, {%4,%5,%6,%7}, {%8,%9}, {%0,%1,%2,%3};"
        : "+f"(c[0]), "+f"(c[1]), "+f"(c[2]), "+f"(c[3])
        : "r"(a[0]), "r"(a[1]), "r"(a[2]), "r"(a[3]), "r"(b[0]), "r"(b[1]));
}
__device__ __forceinline__ void cpa16(uint32_t dst, const void* src) {
    asm volatile("cp.async.cg.shared.global [%0], [%1], 16;" :: "r"(dst), "l"(src));
}
__device__ __forceinline__ void cpa_commit() {
    asm volatile("cp.async.commit_group;" ::: "memory");
}
template <int N>
__device__ __forceinline__ void cpa_wait() {
    asm volatile("cp.async.wait_group %0;" :: "n"(N) : "memory");
}
// 128B rows, 16B granules: col16 ^= row&7
__device__ __forceinline__ uint32_t swz(int row, int c16) {
    return (uint32_t)(((row << 3) + (c16 ^ (row & 7))) << 4);
}

// ================= hidden-layer GEMM: pure-copy staging + mma.sync =================
__device__ __forceinline__ void stage_mma(
    uint32_t tb, const bf16* __restrict__ AH, const bf16* __restrict__ AL,
    const bf16* __restrict__ WH, const bf16* __restrict__ WL, int c)
{
    const int tid = threadIdx.x;
    {   // A: 64 rows x 8 granules, hi+lo
        const int row = tid >> 3, g = tid & 7;
        const uint32_t o = swz(row, g);
        const size_t so = (size_t)row * XX + (c << 6) + (g << 3);
        cpa16(tb + A_HI + o, AH + so);
        cpa16(tb + A_LO + o, AL + so);
    }
#pragma unroll
    for (int r = 0; r < 2; ++r) {   // B: 128 rows x 8 granules, hi+lo
        const int row = (tid >> 3) + (r << 6), g = tid & 7;
        const uint32_t o = swz(row, g);
        const size_t so = (size_t)row * (2 * XX) + (c << 6) + (g << 3);
        cpa16(tb + B_HI + o, WH + so);
        cpa16(tb + B_LO + o, WL + so);
    }
}

__device__ __forceinline__ void gemm_hidden_tc(
    const bf16* __restrict__ A1H, const bf16* __restrict__ A1L,
    const bf16* __restrict__ A2H, const bf16* __restrict__ A2L,
    const bf16* __restrict__ WHl, const bf16* __restrict__ WLl,
    uint32_t tu0)
{
    const int ntile = blockIdx.x >> 3;   // 0..15 (128 n)
    const int ks    = blockIdx.x & 7;    // 0..7  (K=512)
    const int n0    = ntile << 7;
    const int kbeg  = ks << 9;

    const bf16 *AH, *AL;
    if (ks < 4) { AH = A1H + kbeg;        AL = A1L + kbeg; }
    else        { AH = A2H + (kbeg - XX); AL = A2L + (kbeg - XX); }
    const bf16* WH = WHl + (size_t)n0 * (2 * XX) + kbeg;
    const bf16* WL = WLl + (size_t)n0 * (2 * XX) + kbeg;

    const int lane = threadIdx.x & 31, warp = threadIdx.x >> 5;
    const int wx = warp & 7, wy = warp >> 3;   // n-octant(16), m-half(32)

    float acc[2][2][4];
#pragma unroll
    for (int i = 0; i < 2; ++i)
#pragma unroll
        for (int t = 0; t < 2; ++t)
#pragma unroll
            for (int e = 0; e < 4; ++e) acc[i][t][e] = 0.0f;

    stage_mma(tu0, AH, AL, WH, WL, 0);
    cpa_commit();

    const int arow = lane & 15, acb = lane >> 4;
    const int brow = (lane & 7) + ((lane >> 4) << 3), bcb = (lane >> 3) & 1;

    for (int c = 0; c < 8; ++c) {
        if (c < 7) {
            stage_mma(tu0 + ((c + 1) & 1) * TILE_BUF, AH, AL, WH, WL, c + 1);
            cpa_commit();
            cpa_wait<1>();
        } else {
            cpa_wait<0>();
        }
        __syncthreads();

        const uint32_t sb = tu0 + (c & 1) * TILE_BUF;
#pragma unroll
        for (int kk = 0; kk < 4; ++kk) {
            uint32_t ah[2][4], al_[2][4], bh[4], bl_[4];
#pragma unroll
            for (int i = 0; i < 2; ++i) {
                const int row = wy * 32 + i * 16 + arow;
                const uint32_t o = swz(row, kk * 2 + acb);
                ldsm4(ah[i],  sb + A_HI + o);
                ldsm4(al_[i], sb + A_LO + o);
            }
            {
                const int row = wx * 16 + brow;
                const uint32_t o = swz(row, kk * 2 + bcb);
                ldsm4(bh,  sb + B_HI + o);
                ldsm4(bl_, sb + B_LO + o);
            }
#pragma unroll
            for (int i = 0; i < 2; ++i)
#pragma unroll
                for (int t = 0; t < 2; ++t) {
                    mma16816(acc[i][t], ah[i],  &bh[t * 2]);
                    mma16816(acc[i][t], ah[i],  &bl_[t * 2]);
                    mma16816(acc[i][t], al_[i], &bh[t * 2]);
                }
        }
        __syncthreads();
    }

    float* dst = g_part + (size_t)ks * BBXX + n0;
#pragma unroll
    for (int i = 0; i < 2; ++i) {
        const int row = wy * 32 + i * 16 + (lane >> 2);
#pragma unroll
        for (int t = 0; t < 2; ++t) {
            const int col = wx * 16 + t * 8 + (lane & 3) * 2;
            *(float2*)(dst + (size_t)row * XX + col)       = make_float2(acc[i][t][0], acc[i][t][1]);
            *(float2*)(dst + (size_t)(row + 8) * XX + col) = make_float2(acc[i][t][2], acc[i][t][3]);
        }
    }
}

// ---------- reduce: 8 slices (A1: 0-3, A2: 4-7 * sc_b) + bias + act + split ----------
__device__ __forceinline__ void reduce8(
    const float* __restrict__ bias, const int* __restrict__ ids,
    float* __restrict__ dstF, bf16* __restrict__ dstH, bf16* __restrict__ dstL,
    const float* __restrict__ ss_sc, float* ss_out, float* ss_zero, float* sred)
{
    const int gid = blockIdx.x * NTHR + threadIdx.x;   // 0..65535 (= BBXX/2)
    if (ss_zero != nullptr && gid < BB) ss_zero[gid] = 0.0f;
    const int b = gid >> 10;
    const int n = (gid & 1023) << 1;
    const float* p = g_part + ((size_t)gid << 1);
    float s1x = 0.f, s1y = 0.f, s2x = 0.f, s2y = 0.f;
#pragma unroll
    for (int si = 0; si < 4; ++si) {
        float2 v = __ldcg((const float2*)(p + (size_t)si * BBXX));
        s1x += v.x; s1y += v.y;
    }
#pragma unroll
    for (int si = 4; si < 8; ++si) {
        float2 v = __ldcg((const float2*)(p + (size_t)si * BBXX));
        s2x += v.x; s2y += v.y;
    }
    float sc = 1.0f;
    if (ss_sc != nullptr) {
        float v = __ldcg(ss_sc + b);
        sc = 1.0f / fmaxf(sqrtf(v), 1e-12f);
    }
    const float2 b2 = *(const float2*)(bias + n);
    const int2  id2 = *(const int2*)(ids + n);
    const float ox = act_fn(s1x + sc * s2x + b2.x, id2.x);
    const float oy = act_fn(s1y + sc * s2y + b2.y, id2.y);
    if (dstF != nullptr) *(float2*)(dstF + ((size_t)gid << 1)) = make_float2(ox, oy);
    *(unsigned*)(dstH + ((size_t)gid << 1)) = pkbf(ox, oy);
    const float hx = bfof(ox), hy = bfof(oy);
    *(unsigned*)(dstL + ((size_t)gid << 1)) = pkbf(ox - hx, oy - hy);

    if (ss_out != nullptr) {
        float q = ox * ox + oy * oy;
#pragma unroll
        for (int d = 16; d > 0; d >>= 1) q += __shfl_xor_sync(0xffffffffu, q, d);
        if ((threadIdx.x & 31) == 0) sred[threadIdx.x >> 5] = q;
        __syncthreads();
        if (threadIdx.x == 0) {
            float tot = 0.0f;
#pragma unroll
            for (int w = 0; w < NTHR / 32; ++w) tot += sred[w];
            atomicAdd(ss_out + (blockIdx.x >> 1), tot);   // 2 commutative adds/row
        }
    }
}

// ---------------- weight hi/lo split (once per launch) ----------------
__device__ __forceinline__ void wconv(const float* __restrict__ W) {
    const size_t n = 4ull * XX * 2 * XX;
    for (size_t i = ((size_t)blockIdx.x * NTHR + threadIdx.x) * 4; i < n;
         i += (size_t)NBLK * NTHR * 4) {
        float4 v = __ldcg((const float4*)(W + i));
        float hx = bfof(v.x), hy = bfof(v.y), hz = bfof(v.z), hw = bfof(v.w);
        *(uint2*)((char*)g_WhH + 2 * i) = make_uint2(pkbf(v.x, v.y), pkbf(v.z, v.w));
        *(uint2*)((char*)g_WhL + 2 * i) = make_uint2(pkbf(v.x - hx, v.y - hy),
                                                     pkbf(v.z - hz, v.w - hw));
    }
}

// ================= SIMT pre/post pass (512 threads, 4b x 8n thread tile) =======
__device__ __forceinline__ void gemm_core512(
    const float* __restrict__ A, int lda,
    const float* __restrict__ W, int ldw, int nchunks,
    float2* __restrict__ As2, float* __restrict__ Wss, ull acc[4][4])
{
    const int tid = threadIdx.x;
    const int tx = tid & 31, ty = tid >> 5;            // ty 0..15 (4 rows each)
    const int lrow = tid >> 2, lk = (tid & 3) << 2;    // A loaders (tid<256)
    const int wrow = tid >> 2, wk = (tid & 3) << 2;    // W loaders: rows wrow, wrow+128
    const bool aload = (tid < 256);

    const float* Ag  = A + (size_t)lrow * lda + lk;
    const float* Wg0 = W + (size_t)wrow * ldw + wk;
    const float* Wg1 = Wg0 + (size_t)128 * ldw;

#pragma unroll
    for (int i = 0; i < 4; ++i)
#pragma unroll
        for (int j = 0; j < 4; ++j) acc[i][j] = 0ull;

    {   // stage chunk 0
        if (aload) {
            float4 av = __ldcg((const float4*)Ag);
            As2[(lk + 0) * 66 + lrow] = make_float2(av.x, av.x);
            As2[(lk + 1) * 66 + lrow] = make_float2(av.y, av.y);
            As2[(lk + 2) * 66 + lrow] = make_float2(av.z, av.z);
            As2[(lk + 3) * 66 + lrow] = make_float2(av.w, av.w);
        }
        float4 w0 = __ldcg((const float4*)Wg0), w1 = __ldcg((const float4*)Wg1);
        Wss[(wk + 0) * 260 + wrow] = w0.x; Wss[(wk + 1) * 260 + wrow] = w0.y;
        Wss[(wk + 2) * 260 + wrow] = w0.z; Wss[(wk + 3) * 260 + wrow] = w0.w;
        Wss[(wk + 0) * 260 + wrow + 128] = w1.x; Wss[(wk + 1) * 260 + wrow + 128] = w1.y;
        Wss[(wk + 2) * 260 + wrow + 128] = w1.z; Wss[(wk + 3) * 260 + wrow + 128] = w1.w;
    }
    __syncthreads();

    for (int c = 0; c < nchunks; ++c) {
        float4 av, w0v, w1v;
        const bool more = (c + 1 < nchunks);
        if (more) {
            if (aload) av = __ldcg((const float4*)(Ag + (c + 1) * KC));
            w0v = __ldcg((const float4*)(Wg0 + (c + 1) * KC));
            w1v = __ldcg((const float4*)(Wg1 + (c + 1) * KC));
        }
        const float2* Ab = As2 + (c & 1) * (16 * 66);
        const float*  Wb = Wss + (c & 1) * (16 * 260);
#pragma unroll
        for (int k = 0; k < KC; ++k) {
            const float2* Ak = Ab + k * 66 + (ty << 2);
            ulonglong2 a01 = *(const ulonglong2*)(Ak);
            ulonglong2 a23 = *(const ulonglong2*)(Ak + 2);
            const float* Wk = Wb + k * 260 + (tx << 2);
            ulonglong2 w0 = *(const ulonglong2*)(Wk);
            ulonglong2 w1 = *(const ulonglong2*)(Wk + 128);
            ffma2(acc[0][0], a01.x, w0.x); ffma2(acc[0][1], a01.x, w0.y);
            ffma2(acc[0][2], a01.x, w1.x); ffma2(acc[0][3], a01.x, w1.y);
            ffma2(acc[1][0], a01.y, w0.x); ffma2(acc[1][1], a01.y, w0.y);
            ffma2(acc[1][2], a01.y, w1.x); ffma2(acc[1][3], a01.y, w1.y);
            ffma2(acc[2][0], a23.x, w0.x); ffma2(acc[2][1], a23.x, w0.y);
            ffma2(acc[2][2], a23.x, w1.x); ffma2(acc[2][3], a23.x, w1.y);
            ffma2(acc[3][0], a23.y, w0.x); ffma2(acc[3][1], a23.y, w0.y);
            ffma2(acc[3][2], a23.y, w1.x); ffma2(acc[3][3], a23.y, w1.y);
        }
        if (more) {
            float2* Abn = As2 + ((c + 1) & 1) * (16 * 66);
            float*  Wbn = Wss + ((c + 1) & 1) * (16 * 260);
            if (aload) {
                Abn[(lk + 0) * 66 + lrow] = make_float2(av.x, av.x);
                Abn[(lk + 1) * 66 + lrow] = make_float2(av.y, av.y);
                Abn[(lk + 2) * 66 + lrow] = make_float2(av.z, av.z);
                Abn[(lk + 3) * 66 + lrow] = make_float2(av.w, av.w);
            }
            Wbn[(wk + 0) * 260 + wrow] = w0v.x; Wbn[(wk + 1) * 260 + wrow] = w0v.y;
            Wbn[(wk + 2) * 260 + wrow] = w0v.z; Wbn[(wk + 3) * 260 + wrow] = w0v.w;
            Wbn[(wk + 0) * 260 + wrow + 128] = w1v.x; Wbn[(wk + 1) * 260 + wrow + 128] = w1v.y;
            Wbn[(wk + 2) * 260 + wrow + 128] = w1v.z; Wbn[(wk + 3) * 260 + wrow + 128] = w1v.w;
            __syncthreads();
        }
    }
}

__device__ __forceinline__ void prepass(const float* __restrict__ x,
                                        const float* __restrict__ Win,
                                        const float* __restrict__ bin,
                                        const int* __restrict__ ids0,
                                        float2* As2, float* Wss)
{
    for (int tile = blockIdx.x; tile < TT * 8; tile += NBLK) {
        const int t = tile >> 3, n0 = (tile & 7) << 8;
        ull acc[4][4];
        gemm_core512(x + (size_t)t * INF, TT * INF,
                     Win + (size_t)n0 * INF, INF, INF / KC, As2, Wss, acc);
        const int tx = threadIdx.x & 31, ty = threadIdx.x >> 5;
        const int c0 = n0 + (tx << 2);
        float4 b0 = *(const float4*)(bin + c0), b1 = *(const float4*)(bin + c0 + 128);
        int4 i0 = *(const int4*)(ids0 + c0), i1 = *(const int4*)(ids0 + c0 + 128);
        const size_t rb = (size_t)t * BBXX + (size_t)(ty << 2) * XX + c0;
#pragma unroll
        for (int r = 0; r < 4; ++r) {
            float4 v0 = unpack4(acc[r][0], acc[r][1]);
            float4 v1 = unpack4(acc[r][2], acc[r][3]);
            v0.x = act_fn(v0.x + b0.x, i0.x); v0.y = act_fn(v0.y + b0.y, i0.y);
            v0.z = act_fn(v0.z + b0.z, i0.z); v0.w = act_fn(v0.w + b0.w, i0.w);
            v1.x = act_fn(v1.x + b1.x, i1.x); v1.y = act_fn(v1.y + b1.y, i1.y);
            v1.z = act_fn(v1.z + b1.z, i1.z); v1.w = act_fn(v1.w + b1.w, i1.w);
            const size_t o = rb + (size_t)r * XX;
            *(uint2*)(g_h0H + o) = make_uint2(pkbf(v0.x, v0.y), pkbf(v0.z, v0.w));
            *(uint2*)(g_h0L + o) = make_uint2(pkbf(v0.x - bfof(v0.x), v0.y - bfof(v0.y)),
                                              pkbf(v0.z - bfof(v0.z), v0.w - bfof(v0.w)));
            *(uint2*)(g_h0H + o + 128) = make_uint2(pkbf(v1.x, v1.y), pkbf(v1.z, v1.w));
            *(uint2*)(g_h0L + o + 128) = make_uint2(pkbf(v1.x - bfof(v1.x), v1.y - bfof(v1.y)),
                                                    pkbf(v1.z - bfof(v1.z), v1.w - bfof(v1.w)));
        }
    }
}

__device__ __forceinline__ void postpass(const float* __restrict__ Wout,
                                         const float* __restrict__ bout,
                                         const int* __restrict__ oids,
                                         float* __restrict__ out,
                                         float2* As2, float* Wss)
{
    for (int t = blockIdx.x; t < TT; t += NBLK) {
        ull acc[4][4];
        gemm_core512(g_h4all + (size_t)t * BBXX, XX, Wout, XX, XX / KC, As2, Wss, acc);
        const int tx = threadIdx.x & 31, ty = threadIdx.x >> 5;
        const int c0 = tx << 2;
        float4 b0 = *(const float4*)(bout + c0), b1 = *(const float4*)(bout + c0 + 128);
        int4 i0 = *(const int4*)(oids + c0), i1 = *(const int4*)(oids + c0 + 128);
#pragma unroll
        for (int r = 0; r < 4; ++r) {
            const int b = (ty << 2) + r;
            float* dst = out + (size_t)b * (TT * OUTF) + (size_t)t * OUTF + c0;
            float4 v0 = unpack4(acc[r][0], acc[r][1]);
            float4 v1 = unpack4(acc[r][2], acc[r][3]);
            v0.x = act_fn(v0.x + b0.x, i0.x); v0.y = act_fn(v0.y + b0.y, i0.y);
            v0.z = act_fn(v0.z + b0.z, i0.z); v0.w = act_fn(v0.w + b0.w, i0.w);
            v1.x = act_fn(v1.x + b1.x, i1.x); v1.y = act_fn(v1.y + b1.y, i1.y);
            v1.z = act_fn(v1.z + b1.z, i1.z); v1.w = act_fn(v1.w + b1.w, i1.w);
            *(float4*)dst = v0; *(float4*)(dst + 128) = v1;
        }
    }
}

// ---------------- persistent mega-kernel ----------------
__global__ void __launch_bounds__(NTHR, 1)
bnn_kernel(const float* __restrict__ x,     const float* __restrict__ Win,
           const float* __restrict__ bin,   const float* __restrict__ Wh,
           const float* __restrict__ bh,    const float* __restrict__ Wout,
           const float* __restrict__ bout,  const int* __restrict__ act_ids,
           const int* __restrict__ out_ids, float* __restrict__ out)
{
    extern __shared__ char smraw[];
    const uint32_t sbase = smem_u32(smraw);
    const uint32_t tu0 = (sbase + 1023u) & ~1023u;
    char* tiles = smraw + (tu0 - sbase);
    float* sred = (float*)(tiles + OFF_SRED);
    float2* As2 = (float2*)tiles;
    float*  Wss = (float*)(tiles + AS2_BYTES);

    unsigned gen = g_bar_gen;

    // fresh state each launch
    if (blockIdx.x == 0 && threadIdx.x < 256) {
        if (threadIdx.x < 128)      ((float*)g_liss)[threadIdx.x] = 0.0f;
        else                        ((float*)g_bpss)[threadIdx.x - 128] = 0.0f;
    }
    for (int i = blockIdx.x * NTHR + threadIdx.x; i < BBXX; i += NBLK * NTHR) {
        g_h4H[i] = __ushort_as_bfloat16(0); g_h4L[i] = __ushort_as_bfloat16(0);
        g_h2H[1][i] = __ushort_as_bfloat16(0); g_h2L[1][i] = __ushort_as_bfloat16(0);
    }
    wconv(Wh);
    prepass(x, Win, bin, act_ids, As2, Wss);
    grid_sync(gen);

    const size_t WH = (size_t)XX * 2 * XX;
    for (int t = 0; t < TT; ++t) {
        const int p = t & 1, q = p ^ 1;
        const size_t toff = (size_t)t * BBXX;
        const size_t poff = (t > 0) ? (toff - BBXX) : 0;

        // h1 = act([h0 | bp] Wh0^T + bh0),  bp-scale applied in reduce
        gemm_hidden_tc(g_h0H + toff, g_h0L + toff, g_h4H + poff, g_h4L + poff,
                       g_WhH, g_WhL, tu0);
        grid_sync(gen);
        reduce8(bh, act_ids + XX, nullptr, g_h1H, g_h1L,
                (const float*)g_bpss[q], nullptr, nullptr, sred);
        grid_sync(gen);

        // h2 = act([h1 | li] Wh1^T + bh1)
        gemm_hidden_tc(g_h1H, g_h1L, g_h2H[q], g_h2L[q],
                       g_WhH + WH, g_WhL + WH, tu0);
        grid_sync(gen);
        reduce8(bh + XX, act_ids + 2 * XX, nullptr, g_h2H[p], g_h2L[p],
                (const float*)g_liss[q], (float*)g_liss[p], (float*)g_bpss[q], sred);
        grid_sync(gen);

        // h3 = act([h2 | h1] Wh2^T + bh2)
        gemm_hidden_tc(g_h2H[p], g_h2L[p], g_h1H, g_h1L,
                       g_WhH + 2 * WH, g_WhL + 2 * WH, tu0);
        grid_sync(gen);
        reduce8(bh + 2 * XX, act_ids + 3 * XX, nullptr, g_h3H, g_h3L,
                nullptr, nullptr, (float*)g_liss[q], sred);
        grid_sync(gen);

        // h4 = act([h3 | h2] Wh3^T + bh3)
        gemm_hidden_tc(g_h3H, g_h3L, g_h2H[p], g_h2L[p],
                       g_WhH + 3 * WH, g_WhL + 3 * WH, tu0);
        grid_sync(gen);
        reduce8(bh + 3 * XX, act_ids + 4 * XX, g_h4all + toff,
                g_h4H + toff, g_h4L + toff,
                nullptr, (float*)g_bpss[p], nullptr, sred);
        grid_sync(gen);
    }

    postpass(Wout, bout, out_ids, out, As2, Wss);
}

extern "C" void kernel_launch(void* const* d_in, const int* in_sizes, int n_in,
                              void* d_out, int out_size)
{
    (void)in_sizes; (void)n_in; (void)out_size;
    const float* x       = (const float*)d_in[0];
    const float* W_in    = (const float*)d_in[1];
    const float* b_in    = (const float*)d_in[2];
    const float* W_h     = (const float*)d_in[3];
    const float* b_h     = (const float*)d_in[4];
    const float* W_out   = (const float*)d_in[5];
    const float* b_out   = (const float*)d_in[6];
    const int*   act_ids = (const int*)d_in[7];
    const int*   out_ids = (const int*)d_in[8];
    float*       out     = (float*)d_out;

    cudaFuncSetAttribute(bnn_kernel, cudaFuncAttributeMaxDynamicSharedMemorySize,
                         SMEM_BYTES);
    bnn_kernel<<<NBLK, NTHR, SMEM_BYTES>>>(x, W_in, b_in, W_h, b_h, W_out, b_out,
                                           act_ids, out_ids, out);
}

// round 13
// speedup vs baseline: 3.3256x; 1.1324x over previous
#include <cuda_runtime.h>
#include <cuda_bf16.h>
#include <cstdint>

#define BB   64
#define TT   128
#define INF  512
#define XX   2048
#define OUTF 256
#define NBLK 128
#define NTHR 512
#define KC   16
#define KSL  8
#define BBXX (BB * XX)

typedef unsigned long long ull;
typedef __nv_bfloat16 bf16;

// ---------------- persistent device scratch ----------------
__device__ __align__(16) float g_part[KSL * BBXX];
__device__ __align__(16) float g_h4all[TT * BBXX];            // fp32 for postpass
__device__ __align__(16) bf16  g_h0H[TT * BBXX], g_h0L[TT * BBXX];
__device__ __align__(16) bf16  g_h4H[TT * BBXX], g_h4L[TT * BBXX];
__device__ __align__(16) bf16  g_h1H[BBXX], g_h1L[BBXX];
__device__ __align__(16) bf16  g_h2H[2][BBXX], g_h2L[2][BBXX];
__device__ __align__(16) bf16  g_h3H[BBXX], g_h3L[BBXX];
__device__ __align__(16) bf16  g_WhH[4ull * XX * 2 * XX];     // 64MB hi
__device__ __align__(16) bf16  g_WhL[4ull * XX * 2 * XX];     // 64MB lo
__device__ __align__(16) bf16  g_WiH[(size_t)XX * INF], g_WiL[(size_t)XX * INF];
__device__ __align__(16) bf16  g_xH[(size_t)BB * TT * INF], g_xL[(size_t)BB * TT * INF];
__device__ float g_liss[2][BB];
__device__ float g_bpss[2][BB];
__device__ unsigned g_bar_count;
__device__ volatile unsigned g_bar_gen;

// smem (rel. 1024-aligned base): 4 bufs x 48K {Ahi 8K|Alo 8K|Bhi 16K|Blo 16K}
// postpass overlays As2/Wss; sred at 196608.
#define TILE_BUF 49152
#define NBUF 4
#define A_HI 0
#define A_LO 8192
#define B_HI 16384
#define B_LO 32768
#define OFF_SRED (NBUF * TILE_BUF)
#define AS2_BYTES (2 * 16 * 66 * 8)
#define SMEM_BYTES (NBUF * TILE_BUF + 2048 + 1024)

// ---------------- grid barrier ----------------
__device__ __forceinline__ void grid_sync(unsigned& gen) {
    __syncthreads();
    if (threadIdx.x == 0) {
        __threadfence();
        if (atomicAdd(&g_bar_count, 1u) == (unsigned)(NBLK - 1)) {
            g_bar_count = 0u;
            __threadfence();
            g_bar_gen = gen + 1u;
        } else {
            while (g_bar_gen == gen) { }
        }
        __threadfence();
    }
    __syncthreads();
    ++gen;
}

// ---------------- helpers ----------------
__device__ __forceinline__ uint32_t smem_u32(const void* p) {
    uint32_t a;
    asm("{ .reg .u64 t; cvta.to.shared.u64 t, %1; cvt.u32.u64 %0, t; }" : "=r"(a) : "l"(p));
    return a;
}
__device__ __forceinline__ void ffma2(ull& d, ull a, ull b) {
    asm("fma.rn.f32x2 %0, %1, %2, %0;" : "+l"(d) : "l"(a), "l"(b));
}
__device__ __forceinline__ float4 unpack4(ull p, ull q) {
    float4 o;
    o.x = __uint_as_float((unsigned)p);  o.y = __uint_as_float((unsigned)(p >> 32));
    o.z = __uint_as_float((unsigned)q);  o.w = __uint_as_float((unsigned)(q >> 32));
    return o;
}
__device__ __forceinline__ unsigned pkbf(float a, float b) {
    return (unsigned)__bfloat16_as_ushort(__float2bfloat16(a))
         | ((unsigned)__bfloat16_as_ushort(__float2bfloat16(b)) << 16);
}
__device__ __forceinline__ float bfof(float a) {
    return __bfloat162float(__float2bfloat16(a));
}
__device__ __forceinline__ float act_fn(float h, int id) {
    switch (id) {
        case 0: return fmaxf(h, 0.0f);
        case 1: return 1.0f / (1.0f + expf(-h));
        case 2: return tanhf(h);
        case 3: return (h >= 0.0f) ? h : 0.1f * h;
        default: {
            const float sc = 1.0507009873554804934193349852946f;
            const float al = 1.6732632423543772848170429916717f;
            return (h > 0.0f) ? sc * h : sc * al * expm1f(h);
        }
    }
}

// ---------------- tensor-core / async primitives (baseline PTX) ----------------
__device__ __forceinline__ void ldsm4(uint32_t* r, uint32_t addr) {
    asm volatile("ldmatrix.sync.aligned.m8n8.x4.shared.b16 {%0,%1,%2,%3}, [%4];"
                 : "=r"(r[0]), "=r"(r[1]), "=r"(r[2]), "=r"(r[3]) : "r"(addr));
}
__device__ __forceinline__ void mma16816(float* c, const uint32_t* a, const uint32_t* b) {
    asm volatile(
        "mma.sync.aligned.m16n8k16.row.col.f32.bf16.bf16.f32 "
        "{%0,%1,%2,%3}, {%4,%5,%6,%7}, {%8,%9}, {%0,%1,%2,%3};"
        : "+f"(c[0]), "+f"(c[1]), "+f"(c[2]), "+f"(c[3])
        : "r"(a[0]), "r"(a[1]), "r"(a[2]), "r"(a[3]), "r"(b[0]), "r"(b[1]));
}
__device__ __forceinline__ void cpa16(uint32_t dst, const void* src) {
    asm volatile("cp.async.cg.shared.global [%0], [%1], 16;" :: "r"(dst), "l"(src));
}
__device__ __forceinline__ void cpa_commit() {
    asm volatile("cp.async.commit_group;" ::: "memory");
}
template <int N>
__device__ __forceinline__ void cpa_wait() {
    asm volatile("cp.async.wait_group %0;" :: "n"(N) : "memory");
}
// 128B rows, 16B granules: col16 ^= row&7
__device__ __forceinline__ uint32_t swz(int row, int c16) {
    return (uint32_t)(((row << 3) + (c16 ^ (row & 7))) << 4);
}

// ================= shared MMA mainloop (64m x 128n x K512, 8 chunks) =================
__device__ __forceinline__ void stage2(
    uint32_t tb, const bf16* __restrict__ AH, const bf16* __restrict__ AL, size_t sA,
    const bf16* __restrict__ WH, const bf16* __restrict__ WL, size_t sW, int c)
{
    const int tid = threadIdx.x;
    const int row = tid >> 3, g = tid & 7;
    const uint32_t o = swz(row, g);
    const size_t sa = (size_t)row * sA + (c << 6) + (g << 3);
    cpa16(tb + A_HI + o, AH + sa);
    cpa16(tb + A_LO + o, AL + sa);
    const size_t sw0 = (size_t)row * sW + (c << 6) + (g << 3);
    cpa16(tb + B_HI + o, WH + sw0);
    cpa16(tb + B_LO + o, WL + sw0);
    const int row2 = row + 64;
    const uint32_t o2 = swz(row2, g);
    const size_t sw1 = (size_t)row2 * sW + (c << 6) + (g << 3);
    cpa16(tb + B_HI + o2, WH + sw1);
    cpa16(tb + B_LO + o2, WL + sw1);
}

__device__ __forceinline__ void compute_chunk(uint32_t sb, int lane, int wx, int wy,
                                              float acc[2][2][4])
{
    const int arow = lane & 15, acb = lane >> 4;
    const int brow = (lane & 7) + ((lane >> 4) << 3), bcb = (lane >> 3) & 1;
#pragma unroll
    for (int kk = 0; kk < 4; ++kk) {
        uint32_t ah[2][4], al_[2][4], bh[4], bl_[4];
#pragma unroll
        for (int i = 0; i < 2; ++i) {
            const int row = wy * 32 + i * 16 + arow;
            const uint32_t o = swz(row, kk * 2 + acb);
            ldsm4(ah[i],  sb + A_HI + o);
            ldsm4(al_[i], sb + A_LO + o);
        }
        {
            const int row = wx * 16 + brow;
            const uint32_t o = swz(row, kk * 2 + bcb);
            ldsm4(bh,  sb + B_HI + o);
            ldsm4(bl_, sb + B_LO + o);
        }
#pragma unroll
        for (int i = 0; i < 2; ++i)
#pragma unroll
            for (int t = 0; t < 2; ++t) {
                mma16816(acc[i][t], ah[i],  &bh[t * 2]);
                mma16816(acc[i][t], ah[i],  &bl_[t * 2]);
                mma16816(acc[i][t], al_[i], &bh[t * 2]);
            }
    }
}

// 4-buffer pipeline, one __syncthreads per chunk.
__device__ __forceinline__ void mma_mainloop(
    const bf16* __restrict__ AH, const bf16* __restrict__ AL, size_t sA,
    const bf16* __restrict__ WH, const bf16* __restrict__ WL, size_t sW,
    uint32_t tu0, int lane, int wx, int wy, float acc[2][2][4])
{
    stage2(tu0 + 0 * TILE_BUF, AH, AL, sA, WH, WL, sW, 0); cpa_commit();
    stage2(tu0 + 1 * TILE_BUF, AH, AL, sA, WH, WL, sW, 1); cpa_commit();
    stage2(tu0 + 2 * TILE_BUF, AH, AL, sA, WH, WL, sW, 2); cpa_commit();
#pragma unroll
    for (int c = 0; c < 8; ++c) {
        if (c <= 5)      cpa_wait<2>();
        else if (c == 6) cpa_wait<1>();
        else             cpa_wait<0>();
        __syncthreads();
        if (c + 3 < 8) {
            stage2(tu0 + ((c + 3) & 3) * TILE_BUF, AH, AL, sA, WH, WL, sW, c + 3);
            cpa_commit();
        }
        compute_chunk(tu0 + (c & 3) * TILE_BUF, lane, wx, wy, acc);
    }
}

// ================= hidden-layer GEMM =================
__device__ __forceinline__ void gemm_hidden_tc(
    const bf16* __restrict__ A1H, const bf16* __restrict__ A1L,
    const bf16* __restrict__ A2H, const bf16* __restrict__ A2L,
    const bf16* __restrict__ WHl, const bf16* __restrict__ WLl,
    uint32_t tu0)
{
    const int ntile = blockIdx.x >> 3;   // 0..15 (128 n)
    const int ks    = blockIdx.x & 7;    // 0..7  (K=512)
    const int n0    = ntile << 7;
    const int kbeg  = ks << 9;

    const bf16 *AH, *AL;
    if (ks < 4) { AH = A1H + kbeg;        AL = A1L + kbeg; }
    else        { AH = A2H + (kbeg - XX); AL = A2L + (kbeg - XX); }
    const bf16* WH = WHl + (size_t)n0 * (2 * XX) + kbeg;
    const bf16* WL = WLl + (size_t)n0 * (2 * XX) + kbeg;

    const int lane = threadIdx.x & 31, warp = threadIdx.x >> 5;
    const int wx = warp & 7, wy = warp >> 3;

    float acc[2][2][4];
#pragma unroll
    for (int i = 0; i < 2; ++i)
#pragma unroll
        for (int t = 0; t < 2; ++t)
#pragma unroll
            for (int e = 0; e < 4; ++e) acc[i][t][e] = 0.0f;

    mma_mainloop(AH, AL, XX, WH, WL, 2 * XX, tu0, lane, wx, wy, acc);

    float* dst = g_part + (size_t)ks * BBXX + n0;
#pragma unroll
    for (int i = 0; i < 2; ++i) {
        const int row = wy * 32 + i * 16 + (lane >> 2);
#pragma unroll
        for (int t = 0; t < 2; ++t) {
            const int col = wx * 16 + t * 8 + (lane & 3) * 2;
            *(float2*)(dst + (size_t)row * XX + col)       = make_float2(acc[i][t][0], acc[i][t][1]);
            *(float2*)(dst + (size_t)(row + 8) * XX + col) = make_float2(acc[i][t][2], acc[i][t][3]);
        }
    }
}

// ================= pre-pass via mma: h0(t) for all t =================
__device__ __forceinline__ void prepass_tc(
    const float* __restrict__ bin, const int* __restrict__ ids0, uint32_t tu0)
{
    const int lane = threadIdx.x & 31, warp = threadIdx.x >> 5;
    const int wx = warp & 7, wy = warp >> 3;

    for (int job = blockIdx.x; job < TT * 16; job += NBLK) {
        const int t  = job >> 4;
        const int n0 = (job & 15) << 7;
        const bf16* AH = g_xH + (size_t)t * INF;
        const bf16* AL = g_xL + (size_t)t * INF;
        const bf16* WH = g_WiH + (size_t)n0 * INF;
        const bf16* WL = g_WiL + (size_t)n0 * INF;

        float acc[2][2][4];
#pragma unroll
        for (int i = 0; i < 2; ++i)
#pragma unroll
            for (int tt = 0; tt < 2; ++tt)
#pragma unroll
                for (int e = 0; e < 4; ++e) acc[i][tt][e] = 0.0f;

        mma_mainloop(AH, AL, (size_t)TT * INF, WH, WL, INF, tu0, lane, wx, wy, acc);

#pragma unroll
        for (int i = 0; i < 2; ++i) {
            const int r0 = wy * 32 + i * 16 + (lane >> 2);
#pragma unroll
            for (int t8 = 0; t8 < 2; ++t8) {
                const int c0 = n0 + wx * 16 + t8 * 8 + ((lane & 3) << 1);
                const float2 bb = *(const float2*)(bin + c0);
                const int2  ii = *(const int2*)(ids0 + c0);
                const float vx = act_fn(acc[i][t8][0] + bb.x, ii.x);
                const float vy = act_fn(acc[i][t8][1] + bb.y, ii.y);
                const float vz = act_fn(acc[i][t8][2] + bb.x, ii.x);
                const float vw = act_fn(acc[i][t8][3] + bb.y, ii.y);
                const size_t o0 = (size_t)t * BBXX + (size_t)r0 * XX + c0;
                const size_t o1 = o0 + (size_t)8 * XX;
                *(unsigned*)(g_h0H + o0) = pkbf(vx, vy);
                *(unsigned*)(g_h0L + o0) = pkbf(vx - bfof(vx), vy - bfof(vy));
                *(unsigned*)(g_h0H + o1) = pkbf(vz, vw);
                *(unsigned*)(g_h0L + o1) = pkbf(vz - bfof(vz), vw - bfof(vw));
            }
        }
    }
}

// ---------- reduce: 8 slices (A1: 0-3, A2: 4-7 * sc_b) + bias + act + split ----------
__device__ __forceinline__ void reduce8(
    const float* __restrict__ bias, const int* __restrict__ ids,
    float* __restrict__ dstF, bf16* __restrict__ dstH, bf16* __restrict__ dstL,
    const float* __restrict__ ss_sc, float* ss_out, float* ss_zero, float* sred)
{
    const int gid = blockIdx.x * NTHR + threadIdx.x;   // 0..65535 (= BBXX/2)
    if (ss_zero != nullptr && gid < BB) ss_zero[gid] = 0.0f;
    const int b = gid >> 10;
    const int n = (gid & 1023) << 1;
    const float* p = g_part + ((size_t)gid << 1);
    float s1x = 0.f, s1y = 0.f, s2x = 0.f, s2y = 0.f;
#pragma unroll
    for (int si = 0; si < 4; ++si) {
        float2 v = __ldcg((const float2*)(p + (size_t)si * BBXX));
        s1x += v.x; s1y += v.y;
    }
#pragma unroll
    for (int si = 4; si < 8; ++si) {
        float2 v = __ldcg((const float2*)(p + (size_t)si * BBXX));
        s2x += v.x; s2y += v.y;
    }
    float sc = 1.0f;
    if (ss_sc != nullptr) {
        float v = __ldcg(ss_sc + b);
        sc = 1.0f / fmaxf(sqrtf(v), 1e-12f);
    }
    const float2 b2 = *(const float2*)(bias + n);
    const int2  id2 = *(const int2*)(ids + n);
    const float ox = act_fn(s1x + sc * s2x + b2.x, id2.x);
    const float oy = act_fn(s1y + sc * s2y + b2.y, id2.y);
    if (dstF != nullptr) *(float2*)(dstF + ((size_t)gid << 1)) = make_float2(ox, oy);
    *(unsigned*)(dstH + ((size_t)gid << 1)) = pkbf(ox, oy);
    const float hx = bfof(ox), hy = bfof(oy);
    *(unsigned*)(dstL + ((size_t)gid << 1)) = pkbf(ox - hx, oy - hy);

    if (ss_out != nullptr) {
        float q = ox * ox + oy * oy;
#pragma unroll
        for (int d = 16; d > 0; d >>= 1) q += __shfl_xor_sync(0xffffffffu, q, d);
        if ((threadIdx.x & 31) == 0) sred[threadIdx.x >> 5] = q;
        __syncthreads();
        if (threadIdx.x == 0) {
            float tot = 0.0f;
#pragma unroll
            for (int w = 0; w < NTHR / 32; ++w) tot += sred[w];
            atomicAdd(ss_out + (blockIdx.x >> 1), tot);   // 2 commutative adds/row
        }
    }
}

// ---------------- hi/lo split of an fp32 array (grid-wide) ----------------
__device__ __forceinline__ void split_arr(const float* __restrict__ src,
                                          bf16* __restrict__ H, bf16* __restrict__ L,
                                          size_t n)
{
    for (size_t i = ((size_t)blockIdx.x * NTHR + threadIdx.x) * 4; i < n;
         i += (size_t)NBLK * NTHR * 4) {
        float4 v = __ldcg((const float4*)(src + i));
        float hx = bfof(v.x), hy = bfof(v.y), hz = bfof(v.z), hw = bfof(v.w);
        *(uint2*)((char*)H + 2 * i) = make_uint2(pkbf(v.x, v.y), pkbf(v.z, v.w));
        *(uint2*)((char*)L + 2 * i) = make_uint2(pkbf(v.x - hx, v.y - hy),
                                                 pkbf(v.z - hz, v.w - hw));
    }
}

// ================= SIMT post pass (512 threads, 4b x 8n thread tile) =======
__device__ __forceinline__ void gemm_core512(
    const float* __restrict__ A, int lda,
    const float* __restrict__ W, int ldw, int nchunks,
    float2* __restrict__ As2, float* __restrict__ Wss, ull acc[4][4])
{
    const int tid = threadIdx.x;
    const int tx = tid & 31, ty = tid >> 5;
    const int lrow = tid >> 2, lk = (tid & 3) << 2;
    const int wrow = tid >> 2, wk = (tid & 3) << 2;
    const bool aload = (tid < 256);

    const float* Ag  = A + (size_t)lrow * lda + lk;
    const float* Wg0 = W + (size_t)wrow * ldw + wk;
    const float* Wg1 = Wg0 + (size_t)128 * ldw;

#pragma unroll
    for (int i = 0; i < 4; ++i)
#pragma unroll
        for (int j = 0; j < 4; ++j) acc[i][j] = 0ull;

    {
        if (aload) {
            float4 av = __ldcg((const float4*)Ag);
            As2[(lk + 0) * 66 + lrow] = make_float2(av.x, av.x);
            As2[(lk + 1) * 66 + lrow] = make_float2(av.y, av.y);
            As2[(lk + 2) * 66 + lrow] = make_float2(av.z, av.z);
            As2[(lk + 3) * 66 + lrow] = make_float2(av.w, av.w);
        }
        float4 w0 = __ldcg((const float4*)Wg0), w1 = __ldcg((const float4*)Wg1);
        Wss[(wk + 0) * 260 + wrow] = w0.x; Wss[(wk + 1) * 260 + wrow] = w0.y;
        Wss[(wk + 2) * 260 + wrow] = w0.z; Wss[(wk + 3) * 260 + wrow] = w0.w;
        Wss[(wk + 0) * 260 + wrow + 128] = w1.x; Wss[(wk + 1) * 260 + wrow + 128] = w1.y;
        Wss[(wk + 2) * 260 + wrow + 128] = w1.z; Wss[(wk + 3) * 260 + wrow + 128] = w1.w;
    }
    __syncthreads();

    for (int c = 0; c < nchunks; ++c) {
        float4 av, w0v, w1v;
        const bool more = (c + 1 < nchunks);
        if (more) {
            if (aload) av = __ldcg((const float4*)(Ag + (c + 1) * KC));
            w0v = __ldcg((const float4*)(Wg0 + (c + 1) * KC));
            w1v = __ldcg((const float4*)(Wg1 + (c + 1) * KC));
        }
        const float2* Ab = As2 + (c & 1) * (16 * 66);
        const float*  Wb = Wss + (c & 1) * (16 * 260);
#pragma unroll
        for (int k = 0; k < KC; ++k) {
            const float2* Ak = Ab + k * 66 + (ty << 2);
            ulonglong2 a01 = *(const ulonglong2*)(Ak);
            ulonglong2 a23 = *(const ulonglong2*)(Ak + 2);
            const float* Wk = Wb + k * 260 + (tx << 2);
            ulonglong2 w0 = *(const ulonglong2*)(Wk);
            ulonglong2 w1 = *(const ulonglong2*)(Wk + 128);
            ffma2(acc[0][0], a01.x, w0.x); ffma2(acc[0][1], a01.x, w0.y);
            ffma2(acc[0][2], a01.x, w1.x); ffma2(acc[0][3], a01.x, w1.y);
            ffma2(acc[1][0], a01.y, w0.x); ffma2(acc[1][1], a01.y, w0.y);
            ffma2(acc[1][2], a01.y, w1.x); ffma2(acc[1][3], a01.y, w1.y);
            ffma2(acc[2][0], a23.x, w0.x); ffma2(acc[2][1], a23.x, w0.y);
            ffma2(acc[2][2], a23.x, w1.x); ffma2(acc[2][3], a23.x, w1.y);
            ffma2(acc[3][0], a23.y, w0.x); ffma2(acc[3][1], a23.y, w0.y);
            ffma2(acc[3][2], a23.y, w1.x); ffma2(acc[3][3], a23.y, w1.y);
        }
        if (more) {
            float2* Abn = As2 + ((c + 1) & 1) * (16 * 66);
            float*  Wbn = Wss + ((c + 1) & 1) * (16 * 260);
            if (aload) {
                Abn[(lk + 0) * 66 + lrow] = make_float2(av.x, av.x);
                Abn[(lk + 1) * 66 + lrow] = make_float2(av.y, av.y);
                Abn[(lk + 2) * 66 + lrow] = make_float2(av.z, av.z);
                Abn[(lk + 3) * 66 + lrow] = make_float2(av.w, av.w);
            }
            Wbn[(wk + 0) * 260 + wrow] = w0v.x; Wbn[(wk + 1) * 260 + wrow] = w0v.y;
            Wbn[(wk + 2) * 260 + wrow] = w0v.z; Wbn[(wk + 3) * 260 + wrow] = w0v.w;
            Wbn[(wk + 0) * 260 + wrow + 128] = w1v.x; Wbn[(wk + 1) * 260 + wrow + 128] = w1v.y;
            Wbn[(wk + 2) * 260 + wrow + 128] = w1v.z; Wbn[(wk + 3) * 260 + wrow + 128] = w1v.w;
            __syncthreads();
        }
    }
}

__device__ __forceinline__ void postpass(const float* __restrict__ Wout,
                                         const float* __restrict__ bout,
                                         const int* __restrict__ oids,
                                         float* __restrict__ out,
                                         float2* As2, float* Wss)
{
    for (int t = blockIdx.x; t < TT; t += NBLK) {
        ull acc[4][4];
        gemm_core512(g_h4all + (size_t)t * BBXX, XX, Wout, XX, XX / KC, As2, Wss, acc);
        const int tx = threadIdx.x & 31, ty = threadIdx.x >> 5;
        const int c0 = tx << 2;
        float4 b0 = *(const float4*)(bout + c0), b1 = *(const float4*)(bout + c0 + 128);
        int4 i0 = *(const int4*)(oids + c0), i1 = *(const int4*)(oids + c0 + 128);
#pragma unroll
        for (int r = 0; r < 4; ++r) {
            const int b = (ty << 2) + r;
            float* dst = out + (size_t)b * (TT * OUTF) + (size_t)t * OUTF + c0;
            float4 v0 = unpack4(acc[r][0], acc[r][1]);
            float4 v1 = unpack4(acc[r][2], acc[r][3]);
            v0.x = act_fn(v0.x + b0.x, i0.x); v0.y = act_fn(v0.y + b0.y, i0.y);
            v0.z = act_fn(v0.z + b0.z, i0.z); v0.w = act_fn(v0.w + b0.w, i0.w);
            v1.x = act_fn(v1.x + b1.x, i1.x); v1.y = act_fn(v1.y + b1.y, i1.y);
            v1.z = act_fn(v1.z + b1.z, i1.z); v1.w = act_fn(v1.w + b1.w, i1.w);
            *(float4*)dst = v0; *(float4*)(dst + 128) = v1;
        }
    }
}

// ---------------- persistent mega-kernel ----------------
__global__ void __launch_bounds__(NTHR, 1)
bnn_kernel(const float* __restrict__ x,     const float* __restrict__ Win,
           const float* __restrict__ bin,   const float* __restrict__ Wh,
           const float* __restrict__ bh,    const float* __restrict__ Wout,
           const float* __restrict__ bout,  const int* __restrict__ act_ids,
           const int* __restrict__ out_ids, float* __restrict__ out)
{
    extern __shared__ char smraw[];
    const uint32_t sbase = smem_u32(smraw);
    const uint32_t tu0 = (sbase + 1023u) & ~1023u;
    char* tiles = smraw + (tu0 - sbase);
    float* sred = (float*)(tiles + OFF_SRED);
    float2* As2 = (float2*)tiles;
    float*  Wss = (float*)(tiles + AS2_BYTES);

    unsigned gen = g_bar_gen;

    // fresh state each launch
    if (blockIdx.x == 0 && threadIdx.x < 256) {
        if (threadIdx.x < 128) ((float*)g_liss)[threadIdx.x] = 0.0f;
        else                   ((float*)g_bpss)[threadIdx.x - 128] = 0.0f;
    }
    for (int i = blockIdx.x * NTHR + threadIdx.x; i < BBXX; i += NBLK * NTHR) {
        g_h4H[i] = __ushort_as_bfloat16(0); g_h4L[i] = __ushort_as_bfloat16(0);
        g_h2H[1][i] = __ushort_as_bfloat16(0); g_h2L[1][i] = __ushort_as_bfloat16(0);
    }
    split_arr(Wh, g_WhH, g_WhL, 4ull * XX * 2 * XX);
    split_arr(Win, g_WiH, g_WiL, (size_t)XX * INF);
    split_arr(x, g_xH, g_xL, (size_t)BB * TT * INF);
    grid_sync(gen);

    prepass_tc(bin, act_ids, tu0);
    grid_sync(gen);

    const size_t WH = (size_t)XX * 2 * XX;
    for (int t = 0; t < TT; ++t) {
        const int p = t & 1, q = p ^ 1;
        const size_t toff = (size_t)t * BBXX;
        const size_t poff = (t > 0) ? (toff - BBXX) : 0;

        // h1 = act([h0 | bp] Wh0^T + bh0),  bp-scale applied in reduce
        gemm_hidden_tc(g_h0H + toff, g_h0L + toff, g_h4H + poff, g_h4L + poff,
                       g_WhH, g_WhL, tu0);
        grid_sync(gen);
        reduce8(bh, act_ids + XX, nullptr, g_h1H, g_h1L,
                (const float*)g_bpss[q], nullptr, nullptr, sred);
        grid_sync(gen);

        // h2 = act([h1 | li] Wh1^T + bh1)
        gemm_hidden_tc(g_h1H, g_h1L, g_h2H[q], g_h2L[q],
                       g_WhH + WH, g_WhL + WH, tu0);
        grid_sync(gen);
        reduce8(bh + XX, act_ids + 2 * XX, nullptr, g_h2H[p], g_h2L[p],
                (const float*)g_liss[q], (float*)g_liss[p], (float*)g_bpss[q], sred);
        grid_sync(gen);

        // h3 = act([h2 | h1] Wh2^T + bh2)
        gemm_hidden_tc(g_h2H[p], g_h2L[p], g_h1H, g_h1L,
                       g_WhH + 2 * WH, g_WhL + 2 * WH, tu0);
        grid_sync(gen);
        reduce8(bh + 2 * XX, act_ids + 3 * XX, nullptr, g_h3H, g_h3L,
                nullptr, nullptr, (float*)g_liss[q], sred);
        grid_sync(gen);

        // h4 = act([h3 | h2] Wh3^T + bh3)
        gemm_hidden_tc(g_h3H, g_h3L, g_h2H[p], g_h2L[p],
                       g_WhH + 3 * WH, g_WhL + 3 * WH, tu0);
        grid_sync(gen);
        reduce8(bh + 3 * XX, act_ids + 4 * XX, g_h4all + toff,
                g_h4H + toff, g_h4L + toff,
                nullptr, (float*)g_bpss[p], nullptr, sred);
        grid_sync(gen);
    }

    postpass(Wout, bout, out_ids, out, As2, Wss);
}

extern "C" void kernel_launch(void* const* d_in, const int* in_sizes, int n_in,
                              void* d_out, int out_size)
{
    (void)in_sizes; (void)n_in; (void)out_size;
    const float* x       = (const float*)d_in[0];
    const float* W_in    = (const float*)d_in[1];
    const float* b_in    = (const float*)d_in[2];
    const float* W_h     = (const float*)d_in[3];
    const float* b_h     = (const float*)d_in[4];
    const float* W_out   = (const float*)d_in[5];
    const float* b_out   = (const float*)d_in[6];
    const int*   act_ids = (const int*)d_in[7];
    const int*   out_ids = (const int*)d_in[8];
    float*       out     = (float*)d_out;

    cudaFuncSetAttribute(bnn_kernel, cudaFuncAttributeMaxDynamicSharedMemorySize,
                         SMEM_BYTES);
    bnn_kernel<<<NBLK, NTHR, SMEM_BYTES>>>(x, W_in, b_in, W_h, b_h, W_out, b_out,
                                           act_ids, out_ids, out);
}